// round 9
// baseline (speedup 1.0000x reference)
#include <cuda_runtime.h>
#include <cstdint>

// Problem dims (fixed for this instance)
#define BQ 64
#define TQ 256
#define DQ 300
#define HQ 256      // hidden
#define KQ 37       // tags
#define MBQ (TQ*BQ) // 16384 rows (t*B + b)

typedef unsigned long long ull;

// ---------------- scratch (static device globals; no allocation) ----------------
__device__ float g_xgA[(size_t)MBQ * 1024];  // 64 MB
__device__ float g_xgB[(size_t)MBQ * 1024];  // 64 MB
__device__ float g_h0 [(size_t)MBQ * 512];   // 32 MB
__device__ float g_h1 [(size_t)MBQ * 512];   // 32 MB
__device__ float g_em [(size_t)MBQ * KQ];    // 2.4 MB
__device__ float g_llh[BQ];
__device__ unsigned g_flag[128];             // per-CTA step flags (64 per direction)

// ---------------- helpers ----------------
__device__ __forceinline__ float sigf(float x)   { return 1.0f / (1.0f + __expf(-x)); }
__device__ __forceinline__ float tanh_f(float x) { return 2.0f / (1.0f + __expf(-2.0f * x)) - 1.0f; }

__device__ __forceinline__ ull ffma2(ull a, ull b, ull c) {
    ull d;
    asm("fma.rn.f32x2 %0, %1, %2, %3;" : "=l"(d) : "l"(a), "l"(b), "l"(c));
    return d;
}
__device__ __forceinline__ ull pk2(float lo, float hi) {
    ull r;
    asm("mov.b64 %0, {%1, %2};" : "=l"(r) : "f"(lo), "f"(hi));
    return r;
}
__device__ __forceinline__ float2 unpk2(ull v) {
    float2 r;
    asm("mov.b64 {%0, %1}, %2;" : "=f"(r.x), "=f"(r.y) : "l"(v));
    return r;
}

__global__ void reset_flags_kernel() {
    if (threadIdx.x < 128) g_flag[threadIdx.x] = 0u;
}

// ---------------- GEMM: C[M,N] = A(M,K) * Bw(N,K)^T + bias(N) ----------------
// 128x128 tile, 16-k, 256 threads, 8x8 microtile via FFMA2, global->reg prefetch.
#define GBM 128
#define GBN 128
#define GBK 16

template <bool GATHER>
__global__ void __launch_bounds__(256)
gemm_nt_bias(const float* __restrict__ A, const int* __restrict__ textp,
             const float* __restrict__ Bw, const float* __restrict__ bias,
             float* __restrict__ C, int M, int N, int Kd, int lda)
{
    __shared__ float As[GBK * GBM];
    __shared__ float Bs[GBK * GBN];

    const int tid = threadIdx.x;
    const int m0  = blockIdx.y * GBM;
    const int n0  = blockIdx.x * GBN;
    const int tx  = tid & 15;
    const int ty  = tid >> 4;
    const int lrow = tid >> 1;
    const int lkv0 = (tid & 1) * 2;

    ull acc2[8][4];
    #pragma unroll
    for (int i = 0; i < 8; ++i)
        #pragma unroll
        for (int j = 0; j < 4; ++j) acc2[i][j] = 0ull;

    const float* arow_p;
    {
        const int m = m0 + lrow;
        if (GATHER) {
            const int bb = m & 63;
            const int tt = m >> 6;
            const int tok = textp[bb * TQ + tt];
            arow_p = A + (size_t)tok * lda;
        } else {
            arow_p = A + (size_t)m * lda;
        }
    }
    const int nrow = n0 + lrow;
    const float* brow_p = Bw + (size_t)nrow * Kd;
    const bool bvalid = nrow < N;

    const int Ktiles = (Kd + GBK - 1) / GBK;

    float4 cva[2], cvb[2], nva[2], nvb[2];
    // load tile 0
    #pragma unroll
    for (int q = 0; q < 2; ++q) {
        const int kg = (lkv0 + q) * 4;
        cva[q] = make_float4(0.f, 0.f, 0.f, 0.f);
        cvb[q] = make_float4(0.f, 0.f, 0.f, 0.f);
        if (kg + 3 < Kd) {
            cva[q] = *(const float4*)(arow_p + kg);
            if (bvalid) cvb[q] = *(const float4*)(brow_p + kg);
        }
    }

    for (int kt = 0; kt < Ktiles; ++kt) {
        __syncthreads();
        #pragma unroll
        for (int q = 0; q < 2; ++q) {
            const int kv = lkv0 + q;
            As[(kv * 4 + 0) * GBM + lrow] = cva[q].x;
            As[(kv * 4 + 1) * GBM + lrow] = cva[q].y;
            As[(kv * 4 + 2) * GBM + lrow] = cva[q].z;
            As[(kv * 4 + 3) * GBM + lrow] = cva[q].w;
            Bs[(kv * 4 + 0) * GBN + lrow] = cvb[q].x;
            Bs[(kv * 4 + 1) * GBN + lrow] = cvb[q].y;
            Bs[(kv * 4 + 2) * GBN + lrow] = cvb[q].z;
            Bs[(kv * 4 + 3) * GBN + lrow] = cvb[q].w;
        }
        __syncthreads();
        // prefetch next tile into registers (overlaps compute below)
        if (kt + 1 < Ktiles) {
            #pragma unroll
            for (int q = 0; q < 2; ++q) {
                const int kg = (kt + 1) * GBK + (lkv0 + q) * 4;
                nva[q] = make_float4(0.f, 0.f, 0.f, 0.f);
                nvb[q] = make_float4(0.f, 0.f, 0.f, 0.f);
                if (kg + 3 < Kd) {
                    nva[q] = *(const float4*)(arow_p + kg);
                    if (bvalid) nvb[q] = *(const float4*)(brow_p + kg);
                }
            }
        }
        #pragma unroll
        for (int k = 0; k < GBK; ++k) {
            const float4 a0 = *(const float4*)&As[k * GBM + ty * 4];
            const float4 a1 = *(const float4*)&As[k * GBM + 64 + ty * 4];
            const ulonglong2 b0 = *(const ulonglong2*)&Bs[k * GBN + tx * 4];
            const ulonglong2 b1 = *(const ulonglong2*)&Bs[k * GBN + 64 + tx * 4];
            const ull bv2[4] = {b0.x, b0.y, b1.x, b1.y};
            const float av[8] = {a0.x, a0.y, a0.z, a0.w, a1.x, a1.y, a1.z, a1.w};
            #pragma unroll
            for (int i = 0; i < 8; ++i) {
                const ull av2 = pk2(av[i], av[i]);
                #pragma unroll
                for (int j = 0; j < 4; ++j)
                    acc2[i][j] = ffma2(av2, bv2[j], acc2[i][j]);
            }
        }
        #pragma unroll
        for (int q = 0; q < 2; ++q) { cva[q] = nva[q]; cvb[q] = nvb[q]; }
    }
    #pragma unroll
    for (int i = 0; i < 8; ++i) {
        const int mi = (i < 4) ? (ty * 4 + i) : (64 + ty * 4 + (i - 4));
        const int m  = m0 + mi;
        #pragma unroll
        for (int j = 0; j < 4; ++j) {
            const float2 v = unpk2(acc2[i][j]);
            const int c0 = (j < 2) ? (tx * 4 + 2 * j) : (64 + tx * 4 + 2 * (j - 2));
            if (c0 + 0 + n0 < N) C[(size_t)m * N + n0 + c0 + 0] = v.x + bias[n0 + c0 + 0];
            if (c0 + 1 + n0 < N) C[(size_t)m * N + n0 + c0 + 1] = v.y + bias[n0 + c0 + 1];
        }
    }
}

// ---------------- persistent bidirectional LSTM scan ----------------
// grid = 128 blocks: [0,64) fwd, [64,128) bwd. 256 threads.
// Block owns 4 hidden units x 64 batches; Whh slice lives in REGISTERS.
// Thread map: bgrp=tid>>5 (8 batches), u=(tid>>3)&3 (unit), ks=tid&7 (k-slice).
// Batches processed in two passes of 4 (register pressure).
// Inter-CTA sync: per-CTA flag array (no atomic contention).
#define LSTM_SMEM (64 * 65 * 16)   // hs: float4[64][65]

__global__ void __launch_bounds__(256)
lstm_scan(const float* __restrict__ xgF, const float* __restrict__ xgBk,
          const float* __restrict__ WhhF, const float* __restrict__ WhhB,
          float* __restrict__ hout)
{
    extern __shared__ char sm_raw[];
    float4* hs = (float4*)sm_raw;     // [64][65]

    const int dir = blockIdx.x >> 6;
    const int blk = blockIdx.x & 63;
    const int u0  = blk * 4;
    const int tid = threadIdx.x;
    const int bgrp = tid >> 5;        // 0..7 -> batches bgrp*8 .. +7
    const int u    = (tid >> 3) & 3;
    const int ks   = tid & 7;
    const int unit = u0 + u;
    const int dof  = dir ? 256 : 0;

    const float* xg  = dir ? xgBk : xgF;
    const float* Whh = dir ? WhhB : WhhF;
    volatile unsigned* flg = (volatile unsigned*)(g_flag + dir * 64);

    // ---- Whh slice into registers: w[g][q] = float4 (2x f32x2), kv = ks + q*8 ----
    ull w[4][8][2];
    #pragma unroll
    for (int g = 0; g < 4; ++g)
        #pragma unroll
        for (int q = 0; q < 8; ++q) {
            const int kv = ks + q * 8;
            const ulonglong2 v = *(const ulonglong2*)&Whh[(size_t)(g * 256 + unit) * 256 + kv * 4];
            w[g][q][0] = v.x;
            w[g][q][1] = v.y;
        }

    const bool epi = (ks == 0);
    float cc[8];
    #pragma unroll
    for (int i = 0; i < 8; ++i) cc[i] = 0.0f;

    for (int s = 0; s < TQ; ++s) {
        const int t = dir ? (TQ - 1 - s) : s;

        if (s > 0) {
            // stage h_prev (64 x 256 of this direction) into smem, coalesced
            const int tp = dir ? (t + 1) : (t - 1);
            const float* hb = hout + (size_t)tp * BQ * 512 + dof;
            #pragma unroll
            for (int j = 0; j < 16; ++j) {
                const int idx = tid + j * 256;
                const int b = idx >> 6, kv = idx & 63;
                hs[b * 65 + kv] = *(const float4*)(hb + (size_t)b * 512 + kv * 4);
            }
            __syncthreads();
        }

        const float* xgt = xg + (size_t)t * BQ * 1024;

        #pragma unroll
        for (int pass = 0; pass < 2; ++pass) {
            // prefetch xg for this pass (epilogue lanes only; hidden under matvec)
            float xv[4][4];
            if (epi) {
                #pragma unroll
                for (int bi = 0; bi < 4; ++bi) {
                    const int b = bgrp * 8 + pass * 4 + bi;
                    #pragma unroll
                    for (int g = 0; g < 4; ++g)
                        xv[bi][g] = xgt[(size_t)b * 1024 + g * 256 + unit];
                }
            }

            ull acc2[4][4];
            #pragma unroll
            for (int bi = 0; bi < 4; ++bi)
                #pragma unroll
                for (int g = 0; g < 4; ++g) acc2[bi][g] = 0ull;

            if (s > 0) {
                #pragma unroll
                for (int q = 0; q < 8; ++q) {
                    const int kv = ks + q * 8;
                    ulonglong2 hv[4];
                    #pragma unroll
                    for (int bi = 0; bi < 4; ++bi)
                        hv[bi] = *(const ulonglong2*)&hs[(bgrp * 8 + pass * 4 + bi) * 65 + kv];
                    #pragma unroll
                    for (int bi = 0; bi < 4; ++bi) {
                        acc2[bi][0] = ffma2(hv[bi].x, w[0][q][0], acc2[bi][0]);
                        acc2[bi][0] = ffma2(hv[bi].y, w[0][q][1], acc2[bi][0]);
                        acc2[bi][1] = ffma2(hv[bi].x, w[1][q][0], acc2[bi][1]);
                        acc2[bi][1] = ffma2(hv[bi].y, w[1][q][1], acc2[bi][1]);
                        acc2[bi][2] = ffma2(hv[bi].x, w[2][q][0], acc2[bi][2]);
                        acc2[bi][2] = ffma2(hv[bi].y, w[2][q][1], acc2[bi][2]);
                        acc2[bi][3] = ffma2(hv[bi].x, w[3][q][0], acc2[bi][3]);
                        acc2[bi][3] = ffma2(hv[bi].y, w[3][q][1], acc2[bi][3]);
                    }
                }
            }

            // reduce f32x2 halves + ks lanes (xor 1,2,4) -> result on ks==0 lanes
            float accf[4][4];
            #pragma unroll
            for (int bi = 0; bi < 4; ++bi)
                #pragma unroll
                for (int g = 0; g < 4; ++g) {
                    const float2 v = unpk2(acc2[bi][g]);
                    float a = v.x + v.y;
                    a += __shfl_xor_sync(0xffffffffu, a, 1);
                    a += __shfl_xor_sync(0xffffffffu, a, 2);
                    a += __shfl_xor_sync(0xffffffffu, a, 4);
                    accf[bi][g] = a;
                }

            if (epi) {
                #pragma unroll
                for (int bi = 0; bi < 4; ++bi) {
                    const int i = pass * 4 + bi;
                    const int b = bgrp * 8 + i;
                    const float zi = accf[bi][0] + xv[bi][0];
                    const float zf = accf[bi][1] + xv[bi][1];
                    const float zg = accf[bi][2] + xv[bi][2];
                    const float zo = accf[bi][3] + xv[bi][3];
                    const float ig = sigf(zi), fg = sigf(zf), gg = tanh_f(zg), og = sigf(zo);
                    cc[i] = fg * cc[i] + ig * gg;
                    hout[((size_t)t * BQ + b) * 512 + dof + unit] = og * tanh_f(cc[i]);
                }
            }
        }

        // inter-CTA step barrier (per-CTA flag slots; no atomic contention)
        if (s + 1 < TQ) {
            __threadfence();
            __syncthreads();
            if (tid == 0) flg[blk] = (unsigned)(s + 1);
            if (tid < 64) {
                while (flg[tid] < (unsigned)(s + 1)) { }
            }
            __syncthreads();
        }
    }
}

// ---------------- CRF: one block per batch ----------------
__global__ void __launch_bounds__(64)
crf_kernel(const int* __restrict__ text, const int* __restrict__ sbj,
           const float* __restrict__ em, const float* __restrict__ start_t,
           const float* __restrict__ end_t, const float* __restrict__ trans,
           float* __restrict__ llh)
{
    const int b   = blockIdx.x;
    const int tid = threadIdx.x;
    __shared__ float tr[KQ * KQ];
    __shared__ float sc[KQ];
    for (int i = tid; i < KQ * KQ; i += 64) tr[i] = trans[i];
    if (tid < KQ) sc[tid] = start_t[tid] + em[(size_t)b * KQ + tid];
    __syncthreads();

    for (int t = 1; t < TQ; ++t) {
        const int tok = text[b * TQ + t];
        if (tok != 0) {
            float nv = 0.0f;
            if (tid < KQ) {
                float mx = -1e30f;
                #pragma unroll 1
                for (int j = 0; j < KQ; ++j) mx = fmaxf(mx, sc[j] + tr[j * KQ + tid]);
                float ssum = 0.0f;
                #pragma unroll 1
                for (int j = 0; j < KQ; ++j) ssum += __expf(sc[j] + tr[j * KQ + tid] - mx);
                nv = em[((size_t)t * BQ + b) * KQ + tid] + mx + __logf(ssum);
            }
            __syncthreads();
            if (tid < KQ) sc[tid] = nv;
            __syncthreads();
        }
    }

    if (tid == 0) {
        float mx = -1e30f;
        for (int k = 0; k < KQ; ++k) mx = fmaxf(mx, sc[k] + end_t[k]);
        float ssum = 0.0f;
        for (int k = 0; k < KQ; ++k) ssum += __expf(sc[k] + end_t[k] - mx);
        const float logZ = mx + __logf(ssum);
        int tag0 = sbj[b * TQ + 0];
        float num = start_t[tag0] + em[(size_t)b * KQ + tag0];
        int prev = tag0, last = tag0;
        for (int t = 1; t < TQ; ++t) {
            if (text[b * TQ + t] != 0) {
                const int tg = sbj[b * TQ + t];
                num += em[((size_t)t * BQ + b) * KQ + tg] + tr[prev * KQ + tg];
                prev = tg; last = tg;
            }
        }
        num += end_t[last];
        llh[b] = num - logZ;
    }
}

// ---------------- finalize ----------------
__global__ void __launch_bounds__(256)
finalize_kernel(const int* __restrict__ text, const float* __restrict__ llh,
                float* __restrict__ out)
{
    __shared__ float sred[256];
    __shared__ float cred[256];
    const int tid = threadIdx.x;
    float s = 0.0f, c = 0.0f;
    for (int i = tid; i < BQ; i += 256) s += llh[i];
    for (int i = tid; i < BQ * TQ; i += 256) c += (text[i] != 0) ? 1.0f : 0.0f;
    sred[tid] = s; cred[tid] = c;
    __syncthreads();
    for (int off = 128; off > 0; off >>= 1) {
        if (tid < off) { sred[tid] += sred[tid + off]; cred[tid] += cred[tid + off]; }
        __syncthreads();
    }
    if (tid == 0) out[0] = -(sred[0] / cred[0]);
}

// ---------------- launch ----------------
extern "C" void kernel_launch(void* const* d_in, const int* in_sizes, int n_in,
                              void* d_out, int out_size)
{
    const int*   text  = (const int*)  d_in[0];
    const int*   sbj   = (const int*)  d_in[1];
    const float* emb   = (const float*)d_in[2];
    const float* Wih0f = (const float*)d_in[3];
    const float* Whh0f = (const float*)d_in[4];
    const float* b0f   = (const float*)d_in[5];
    const float* Wih0b = (const float*)d_in[6];
    const float* Whh0b = (const float*)d_in[7];
    const float* b0b   = (const float*)d_in[8];
    const float* Wih1f = (const float*)d_in[9];
    const float* Whh1f = (const float*)d_in[10];
    const float* b1f   = (const float*)d_in[11];
    const float* Wih1b = (const float*)d_in[12];
    const float* Whh1b = (const float*)d_in[13];
    const float* b1b   = (const float*)d_in[14];
    const float* W_sbj = (const float*)d_in[15];
    const float* b_sbj = (const float*)d_in[16];
    const float* st_t  = (const float*)d_in[17];
    const float* en_t  = (const float*)d_in[18];
    const float* trans = (const float*)d_in[19];
    float* out = (float*)d_out;

    float *xgA, *xgB, *h0, *h1, *em, *llh;
    cudaGetSymbolAddress((void**)&xgA, g_xgA);
    cudaGetSymbolAddress((void**)&xgB, g_xgB);
    cudaGetSymbolAddress((void**)&h0,  g_h0);
    cudaGetSymbolAddress((void**)&h1,  g_h1);
    cudaGetSymbolAddress((void**)&em,  g_em);
    cudaGetSymbolAddress((void**)&llh, g_llh);

    cudaFuncSetAttribute(lstm_scan, cudaFuncAttributeMaxDynamicSharedMemorySize, LSTM_SMEM);

    const dim3 gGemmFull(1024 / GBN, MBQ / GBM);   // (8, 128)
    const dim3 gGemmEm(1, MBQ / GBM);              // (1, 128)  N=37

    gemm_nt_bias<true><<<gGemmFull, 256>>>(emb, text, Wih0f, b0f, xgA, MBQ, 1024, DQ, DQ);
    gemm_nt_bias<true><<<gGemmFull, 256>>>(emb, text, Wih0b, b0b, xgB, MBQ, 1024, DQ, DQ);
    reset_flags_kernel<<<1, 128>>>();
    lstm_scan<<<128, 256, LSTM_SMEM>>>(xgA, xgB, Whh0f, Whh0b, h0);

    gemm_nt_bias<false><<<gGemmFull, 256>>>(h0, nullptr, Wih1f, b1f, xgA, MBQ, 1024, 512, 512);
    gemm_nt_bias<false><<<gGemmFull, 256>>>(h0, nullptr, Wih1b, b1b, xgB, MBQ, 1024, 512, 512);
    reset_flags_kernel<<<1, 128>>>();
    lstm_scan<<<128, 256, LSTM_SMEM>>>(xgA, xgB, Whh1f, Whh1b, h1);

    gemm_nt_bias<false><<<gGemmEm, 256>>>(h1, nullptr, W_sbj, b_sbj, em, MBQ, KQ, 512, 512);

    crf_kernel<<<BQ, 64>>>(text, sbj, em, st_t, en_t, trans, llh);
    finalize_kernel<<<1, 256>>>(text, llh, out);
}

// round 10
// speedup vs baseline: 1.0352x; 1.0352x over previous
#include <cuda_runtime.h>
#include <cstdint>

// Problem dims (fixed for this instance)
#define BQ 64
#define TQ 256
#define DQ 300
#define HQ 256      // hidden
#define KQ 37       // tags
#define MBQ (TQ*BQ) // 16384 rows (t*B + b)

typedef unsigned long long ull;

// ---------------- scratch (static device globals; no allocation) ----------------
__device__ float g_xgA[(size_t)MBQ * 1024];  // 64 MB
__device__ float g_xgB[(size_t)MBQ * 1024];  // 64 MB
__device__ float g_h0 [(size_t)MBQ * 512];   // 32 MB
__device__ float g_h1 [(size_t)MBQ * 512];   // 32 MB
__device__ float g_em [(size_t)MBQ * KQ];    // 2.4 MB
__device__ float g_llh[BQ];
__device__ unsigned g_flag[128];             // per-CTA step flags (64 per direction)

// ---------------- helpers ----------------
__device__ __forceinline__ float sigf(float x)   { return 1.0f / (1.0f + __expf(-x)); }
__device__ __forceinline__ float tanh_f(float x) { return 2.0f / (1.0f + __expf(-2.0f * x)) - 1.0f; }

__device__ __forceinline__ ull ffma2(ull a, ull b, ull c) {
    ull d;
    asm("fma.rn.f32x2 %0, %1, %2, %3;" : "=l"(d) : "l"(a), "l"(b), "l"(c));
    return d;
}
__device__ __forceinline__ ull pk2(float lo, float hi) {
    ull r;
    asm("mov.b64 %0, {%1, %2};" : "=l"(r) : "f"(lo), "f"(hi));
    return r;
}
__device__ __forceinline__ float2 unpk2(ull v) {
    float2 r;
    asm("mov.b64 {%0, %1}, %2;" : "=f"(r.x), "=f"(r.y) : "l"(v));
    return r;
}

__global__ void reset_flags_kernel() {
    if (threadIdx.x < 128) g_flag[threadIdx.x] = 0u;
}

// ---------------- GEMM: C[M,N] = A(M,K) * Bw(N,K)^T + bias(N) ----------------
// 128x128 tile, 16-k, 256 threads, 8x8 microtile via FFMA2, global->reg prefetch.
#define GBM 128
#define GBN 128
#define GBK 16

template <bool GATHER>
__global__ void __launch_bounds__(256)
gemm_nt_bias(const float* __restrict__ A, const int* __restrict__ textp,
             const float* __restrict__ Bw, const float* __restrict__ bias,
             float* __restrict__ C, int M, int N, int Kd, int lda)
{
    __shared__ float As[GBK * GBM];
    __shared__ float Bs[GBK * GBN];

    const int tid = threadIdx.x;
    const int m0  = blockIdx.y * GBM;
    const int n0  = blockIdx.x * GBN;
    const int tx  = tid & 15;
    const int ty  = tid >> 4;
    const int lrow = tid >> 1;
    const int lkv0 = (tid & 1) * 2;

    ull acc2[8][4];
    #pragma unroll
    for (int i = 0; i < 8; ++i)
        #pragma unroll
        for (int j = 0; j < 4; ++j) acc2[i][j] = 0ull;

    const float* arow_p;
    {
        const int m = m0 + lrow;
        if (GATHER) {
            const int bb = m & 63;
            const int tt = m >> 6;
            const int tok = textp[bb * TQ + tt];
            arow_p = A + (size_t)tok * lda;
        } else {
            arow_p = A + (size_t)m * lda;
        }
    }
    const int nrow = n0 + lrow;
    const float* brow_p = Bw + (size_t)nrow * Kd;
    const bool bvalid = nrow < N;

    const int Ktiles = (Kd + GBK - 1) / GBK;

    float4 cva[2], cvb[2], nva[2], nvb[2];
    #pragma unroll
    for (int q = 0; q < 2; ++q) {
        const int kg = (lkv0 + q) * 4;
        cva[q] = make_float4(0.f, 0.f, 0.f, 0.f);
        cvb[q] = make_float4(0.f, 0.f, 0.f, 0.f);
        if (kg + 3 < Kd) {
            cva[q] = *(const float4*)(arow_p + kg);
            if (bvalid) cvb[q] = *(const float4*)(brow_p + kg);
        }
    }

    for (int kt = 0; kt < Ktiles; ++kt) {
        __syncthreads();
        #pragma unroll
        for (int q = 0; q < 2; ++q) {
            const int kv = lkv0 + q;
            As[(kv * 4 + 0) * GBM + lrow] = cva[q].x;
            As[(kv * 4 + 1) * GBM + lrow] = cva[q].y;
            As[(kv * 4 + 2) * GBM + lrow] = cva[q].z;
            As[(kv * 4 + 3) * GBM + lrow] = cva[q].w;
            Bs[(kv * 4 + 0) * GBN + lrow] = cvb[q].x;
            Bs[(kv * 4 + 1) * GBN + lrow] = cvb[q].y;
            Bs[(kv * 4 + 2) * GBN + lrow] = cvb[q].z;
            Bs[(kv * 4 + 3) * GBN + lrow] = cvb[q].w;
        }
        __syncthreads();
        if (kt + 1 < Ktiles) {
            #pragma unroll
            for (int q = 0; q < 2; ++q) {
                const int kg = (kt + 1) * GBK + (lkv0 + q) * 4;
                nva[q] = make_float4(0.f, 0.f, 0.f, 0.f);
                nvb[q] = make_float4(0.f, 0.f, 0.f, 0.f);
                if (kg + 3 < Kd) {
                    nva[q] = *(const float4*)(arow_p + kg);
                    if (bvalid) nvb[q] = *(const float4*)(brow_p + kg);
                }
            }
        }
        #pragma unroll
        for (int k = 0; k < GBK; ++k) {
            const float4 a0 = *(const float4*)&As[k * GBM + ty * 4];
            const float4 a1 = *(const float4*)&As[k * GBM + 64 + ty * 4];
            const ulonglong2 b0 = *(const ulonglong2*)&Bs[k * GBN + tx * 4];
            const ulonglong2 b1 = *(const ulonglong2*)&Bs[k * GBN + 64 + tx * 4];
            const ull bv2[4] = {b0.x, b0.y, b1.x, b1.y};
            const float av[8] = {a0.x, a0.y, a0.z, a0.w, a1.x, a1.y, a1.z, a1.w};
            #pragma unroll
            for (int i = 0; i < 8; ++i) {
                const ull av2 = pk2(av[i], av[i]);
                #pragma unroll
                for (int j = 0; j < 4; ++j)
                    acc2[i][j] = ffma2(av2, bv2[j], acc2[i][j]);
            }
        }
        #pragma unroll
        for (int q = 0; q < 2; ++q) { cva[q] = nva[q]; cvb[q] = nvb[q]; }
    }
    #pragma unroll
    for (int i = 0; i < 8; ++i) {
        const int mi = (i < 4) ? (ty * 4 + i) : (64 + ty * 4 + (i - 4));
        const int m  = m0 + mi;
        #pragma unroll
        for (int j = 0; j < 4; ++j) {
            const float2 v = unpk2(acc2[i][j]);
            const int c0 = (j < 2) ? (tx * 4 + 2 * j) : (64 + tx * 4 + 2 * (j - 2));
            if (c0 + 0 + n0 < N) C[(size_t)m * N + n0 + c0 + 0] = v.x + bias[n0 + c0 + 0];
            if (c0 + 1 + n0 < N) C[(size_t)m * N + n0 + c0 + 1] = v.y + bias[n0 + c0 + 1];
        }
    }
}

// ---------------- persistent bidirectional LSTM scan ----------------
// grid = 128 blocks: [0,64) fwd, [64,128) bwd. 256 threads.
// Block owns 4 hidden units x 64 batches; Whh slice in SMEM (R6 structure).
// Thread map: bgrp=tid>>5 (8 batches), u=(tid>>3)&3 (unit), ks=tid&7 (k-slice).
// Reduction routes values so lane ks owns batch bgrp*8+ks -> parallel epilogue.
// Inter-CTA sync: per-CTA flag slots (no atomic contention).
#define LSTM_SMEM (64 * 65 * 16 + 16 * 264 * 4)   // hs float4[64][65] + Ws[16][264]

__global__ void __launch_bounds__(256)
lstm_scan(const float* __restrict__ xgF, const float* __restrict__ xgBk,
          const float* __restrict__ WhhF, const float* __restrict__ WhhB,
          float* __restrict__ hout)
{
    extern __shared__ char sm_raw[];
    float4* hs = (float4*)sm_raw;                     // [64][65]
    float*  Ws = (float*)(sm_raw + 64 * 65 * 16);     // [16][264]

    const int dir = blockIdx.x >> 6;
    const int blk = blockIdx.x & 63;
    const int u0  = blk * 4;
    const int tid = threadIdx.x;
    const int bgrp = tid >> 5;        // 0..7 -> batches bgrp*8 .. +7
    const int u    = (tid >> 3) & 3;
    const int ks   = tid & 7;
    const int unit = u0 + u;
    const int dof  = dir ? 256 : 0;
    const int bb   = bgrp * 8 + ks;   // this thread's epilogue batch

    const float* xg  = dir ? xgBk : xgF;
    const float* Whh = dir ? WhhB : WhhF;
    volatile unsigned* flg = (volatile unsigned*)(g_flag + dir * 64);

    for (int i = tid; i < 16 * 256; i += 256) {
        const int r = i >> 8, k = i & 255;
        const int g = r >> 2, uu = r & 3;
        Ws[r * 264 + k] = Whh[(size_t)(g * 256 + u0 + uu) * 256 + k];
    }
    __syncthreads();

    const float4* wp0 = (const float4*)&Ws[(0 * 4 + u) * 264];
    const float4* wp1 = (const float4*)&Ws[(1 * 4 + u) * 264];
    const float4* wp2 = (const float4*)&Ws[(2 * 4 + u) * 264];
    const float4* wp3 = (const float4*)&Ws[(3 * 4 + u) * 264];

    float cc = 0.0f;

    for (int s = 0; s < TQ; ++s) {
        const int t = dir ? (TQ - 1 - s) : s;

        // xg prefetch: every thread loads the 4 gate inputs for ITS batch/unit
        const float* xr = xg + ((size_t)t * BQ + bb) * 1024 + unit;
        const float xv0 = __ldg(xr + 0);
        const float xv1 = __ldg(xr + 256);
        const float xv2 = __ldg(xr + 512);
        const float xv3 = __ldg(xr + 768);

        ull acc2[8][4];
        #pragma unroll
        for (int i = 0; i < 8; ++i)
            #pragma unroll
            for (int g = 0; g < 4; ++g) acc2[i][g] = 0ull;

        if (s > 0) {
            // stage h_prev (64 x 256 of this direction) into smem, coalesced
            const int tp = dir ? (t + 1) : (t - 1);
            const float* hb = hout + (size_t)tp * BQ * 512 + dof;
            #pragma unroll
            for (int j = 0; j < 16; ++j) {
                const int idx = tid + j * 256;
                const int b = idx >> 6, kv = idx & 63;
                hs[b * 65 + kv] = __ldg((const float4*)(hb + (size_t)b * 512 + kv * 4));
            }
            __syncthreads();
            // mat-vec from smem, k-pairs in f32x2 lanes
            #pragma unroll
            for (int q = 0; q < 8; ++q) {
                const int kv = ks + q * 8;
                const ulonglong2 w0 = *(const ulonglong2*)(wp0 + kv);
                const ulonglong2 w1 = *(const ulonglong2*)(wp1 + kv);
                const ulonglong2 w2 = *(const ulonglong2*)(wp2 + kv);
                const ulonglong2 w3 = *(const ulonglong2*)(wp3 + kv);
                #pragma unroll
                for (int i = 0; i < 8; ++i) {
                    const ulonglong2 h2 = *(const ulonglong2*)&hs[(bgrp * 8 + i) * 65 + kv];
                    acc2[i][0] = ffma2(h2.x, w0.x, acc2[i][0]);
                    acc2[i][0] = ffma2(h2.y, w0.y, acc2[i][0]);
                    acc2[i][1] = ffma2(h2.x, w1.x, acc2[i][1]);
                    acc2[i][1] = ffma2(h2.y, w1.y, acc2[i][1]);
                    acc2[i][2] = ffma2(h2.x, w2.x, acc2[i][2]);
                    acc2[i][2] = ffma2(h2.y, w2.y, acc2[i][2]);
                    acc2[i][3] = ffma2(h2.x, w3.x, acc2[i][3]);
                    acc2[i][3] = ffma2(h2.y, w3.y, acc2[i][3]);
                }
            }
        }

        // ---- value-routed butterfly over ks lanes ----
        // collapse f32x2 halves
        float v8[8][4];
        #pragma unroll
        for (int i = 0; i < 8; ++i)
            #pragma unroll
            for (int g = 0; g < 4; ++g) {
                const float2 p = unpk2(acc2[i][g]);
                v8[i][g] = p.x + p.y;
            }
        // round d=4: keep batches whose bit2 matches lane bit2
        const bool q2 = (ks & 4) != 0;
        float v4[4][4];
        #pragma unroll
        for (int j = 0; j < 4; ++j)
            #pragma unroll
            for (int g = 0; g < 4; ++g) {
                const float snd = q2 ? v8[j][g] : v8[j + 4][g];
                const float got = __shfl_xor_sync(0xffffffffu, snd, 4);
                v4[j][g] = (q2 ? v8[j + 4][g] : v8[j][g]) + got;
            }
        // round d=2
        const bool q1 = (ks & 2) != 0;
        float v2r[2][4];
        #pragma unroll
        for (int j = 0; j < 2; ++j)
            #pragma unroll
            for (int g = 0; g < 4; ++g) {
                const float snd = q1 ? v4[j][g] : v4[j + 2][g];
                const float got = __shfl_xor_sync(0xffffffffu, snd, 2);
                v2r[j][g] = (q1 ? v4[j + 2][g] : v4[j][g]) + got;
            }
        // round d=1
        const bool q0 = (ks & 1) != 0;
        float z[4];
        #pragma unroll
        for (int g = 0; g < 4; ++g) {
            const float snd = q0 ? v2r[0][g] : v2r[1][g];
            const float got = __shfl_xor_sync(0xffffffffu, snd, 1);
            z[g] = (q0 ? v2r[1][g] : v2r[0][g]) + got;
        }

        // ---- fully parallel epilogue: one LSTM cell per thread ----
        {
            const float zi = z[0] + xv0;
            const float zf = z[1] + xv1;
            const float zg = z[2] + xv2;
            const float zo = z[3] + xv3;
            const float ig = sigf(zi), fg = sigf(zf), gg = tanh_f(zg), og = sigf(zo);
            cc = fg * cc + ig * gg;
            hout[((size_t)t * BQ + bb) * 512 + dof + unit] = og * tanh_f(cc);
        }

        // ---- inter-CTA step barrier (per-CTA flag slots) ----
        if (s + 1 < TQ) {
            __threadfence();
            __syncthreads();
            if (tid == 0) flg[blk] = (unsigned)(s + 1);
            if (tid < 64) {
                while (flg[tid] < (unsigned)(s + 1)) { }
            }
            __syncthreads();
        }
    }
}

// ---------------- CRF: one block per batch ----------------
__global__ void __launch_bounds__(64)
crf_kernel(const int* __restrict__ text, const int* __restrict__ sbj,
           const float* __restrict__ em, const float* __restrict__ start_t,
           const float* __restrict__ end_t, const float* __restrict__ trans,
           float* __restrict__ llh)
{
    const int b   = blockIdx.x;
    const int tid = threadIdx.x;
    __shared__ float tr[KQ * KQ];
    __shared__ float sc[KQ];
    for (int i = tid; i < KQ * KQ; i += 64) tr[i] = trans[i];
    if (tid < KQ) sc[tid] = start_t[tid] + em[(size_t)b * KQ + tid];
    __syncthreads();

    for (int t = 1; t < TQ; ++t) {
        const int tok = text[b * TQ + t];
        if (tok != 0) {
            float nv = 0.0f;
            if (tid < KQ) {
                float mx = -1e30f;
                #pragma unroll 1
                for (int j = 0; j < KQ; ++j) mx = fmaxf(mx, sc[j] + tr[j * KQ + tid]);
                float ssum = 0.0f;
                #pragma unroll 1
                for (int j = 0; j < KQ; ++j) ssum += __expf(sc[j] + tr[j * KQ + tid] - mx);
                nv = em[((size_t)t * BQ + b) * KQ + tid] + mx + __logf(ssum);
            }
            __syncthreads();
            if (tid < KQ) sc[tid] = nv;
            __syncthreads();
        }
    }

    if (tid == 0) {
        float mx = -1e30f;
        for (int k = 0; k < KQ; ++k) mx = fmaxf(mx, sc[k] + end_t[k]);
        float ssum = 0.0f;
        for (int k = 0; k < KQ; ++k) ssum += __expf(sc[k] + end_t[k] - mx);
        const float logZ = mx + __logf(ssum);
        int tag0 = sbj[b * TQ + 0];
        float num = start_t[tag0] + em[(size_t)b * KQ + tag0];
        int prev = tag0, last = tag0;
        for (int t = 1; t < TQ; ++t) {
            if (text[b * TQ + t] != 0) {
                const int tg = sbj[b * TQ + t];
                num += em[((size_t)t * BQ + b) * KQ + tg] + tr[prev * KQ + tg];
                prev = tg; last = tg;
            }
        }
        num += end_t[last];
        llh[b] = num - logZ;
    }
}

// ---------------- finalize ----------------
__global__ void __launch_bounds__(256)
finalize_kernel(const int* __restrict__ text, const float* __restrict__ llh,
                float* __restrict__ out)
{
    __shared__ float sred[256];
    __shared__ float cred[256];
    const int tid = threadIdx.x;
    float s = 0.0f, c = 0.0f;
    for (int i = tid; i < BQ; i += 256) s += llh[i];
    for (int i = tid; i < BQ * TQ; i += 256) c += (text[i] != 0) ? 1.0f : 0.0f;
    sred[tid] = s; cred[tid] = c;
    __syncthreads();
    for (int off = 128; off > 0; off >>= 1) {
        if (tid < off) { sred[tid] += sred[tid + off]; cred[tid] += cred[tid + off]; }
        __syncthreads();
    }
    if (tid == 0) out[0] = -(sred[0] / cred[0]);
}

// ---------------- launch ----------------
extern "C" void kernel_launch(void* const* d_in, const int* in_sizes, int n_in,
                              void* d_out, int out_size)
{
    const int*   text  = (const int*)  d_in[0];
    const int*   sbj   = (const int*)  d_in[1];
    const float* emb   = (const float*)d_in[2];
    const float* Wih0f = (const float*)d_in[3];
    const float* Whh0f = (const float*)d_in[4];
    const float* b0f   = (const float*)d_in[5];
    const float* Wih0b = (const float*)d_in[6];
    const float* Whh0b = (const float*)d_in[7];
    const float* b0b   = (const float*)d_in[8];
    const float* Wih1f = (const float*)d_in[9];
    const float* Whh1f = (const float*)d_in[10];
    const float* b1f   = (const float*)d_in[11];
    const float* Wih1b = (const float*)d_in[12];
    const float* Whh1b = (const float*)d_in[13];
    const float* b1b   = (const float*)d_in[14];
    const float* W_sbj = (const float*)d_in[15];
    const float* b_sbj = (const float*)d_in[16];
    const float* st_t  = (const float*)d_in[17];
    const float* en_t  = (const float*)d_in[18];
    const float* trans = (const float*)d_in[19];
    float* out = (float*)d_out;

    float *xgA, *xgB, *h0, *h1, *em, *llh;
    cudaGetSymbolAddress((void**)&xgA, g_xgA);
    cudaGetSymbolAddress((void**)&xgB, g_xgB);
    cudaGetSymbolAddress((void**)&h0,  g_h0);
    cudaGetSymbolAddress((void**)&h1,  g_h1);
    cudaGetSymbolAddress((void**)&em,  g_em);
    cudaGetSymbolAddress((void**)&llh, g_llh);

    cudaFuncSetAttribute(lstm_scan, cudaFuncAttributeMaxDynamicSharedMemorySize, LSTM_SMEM);

    const dim3 gGemmFull(1024 / GBN, MBQ / GBM);   // (8, 128)
    const dim3 gGemmEm(1, MBQ / GBM);              // (1, 128)  N=37

    gemm_nt_bias<true><<<gGemmFull, 256>>>(emb, text, Wih0f, b0f, xgA, MBQ, 1024, DQ, DQ);
    gemm_nt_bias<true><<<gGemmFull, 256>>>(emb, text, Wih0b, b0b, xgB, MBQ, 1024, DQ, DQ);
    reset_flags_kernel<<<1, 128>>>();
    lstm_scan<<<128, 256, LSTM_SMEM>>>(xgA, xgB, Whh0f, Whh0b, h0);

    gemm_nt_bias<false><<<gGemmFull, 256>>>(h0, nullptr, Wih1f, b1f, xgA, MBQ, 1024, 512, 512);
    gemm_nt_bias<false><<<gGemmFull, 256>>>(h0, nullptr, Wih1b, b1b, xgB, MBQ, 1024, 512, 512);
    reset_flags_kernel<<<1, 128>>>();
    lstm_scan<<<128, 256, LSTM_SMEM>>>(xgA, xgB, Whh1f, Whh1b, h1);

    gemm_nt_bias<false><<<gGemmEm, 256>>>(h1, nullptr, W_sbj, b_sbj, em, MBQ, KQ, 512, 512);

    crf_kernel<<<BQ, 64>>>(text, sbj, em, st_t, en_t, trans, llh);
    finalize_kernel<<<1, 256>>>(text, llh, out);
}

// round 11
// speedup vs baseline: 1.9546x; 1.8881x over previous
#include <cuda_runtime.h>
#include <cstdint>

// Problem dims (fixed for this instance)
#define BQ 64
#define TQ 256
#define DQ 300
#define HQ 256      // hidden
#define KQ 37       // tags
#define MBQ (TQ*BQ) // 16384 rows (t*B + b)

typedef unsigned long long ull;

// ---------------- scratch (static device globals; no allocation) ----------------
__device__ float g_xgA[(size_t)MBQ * 1024];  // 64 MB
__device__ float g_xgB[(size_t)MBQ * 1024];  // 64 MB
__device__ float g_h0 [(size_t)MBQ * 512];   // 32 MB
__device__ float g_h1 [(size_t)MBQ * 512];   // 32 MB
__device__ float g_em [(size_t)MBQ * KQ];    // 2.4 MB
__device__ float g_llh[BQ];
__device__ unsigned g_bar[64];               // per-direction barrier counters (padded)

// ---------------- helpers ----------------
__device__ __forceinline__ float sigf(float x)   { return 1.0f / (1.0f + __expf(-x)); }
__device__ __forceinline__ float tanh_f(float x) { return 2.0f / (1.0f + __expf(-2.0f * x)) - 1.0f; }

__device__ __forceinline__ ull ffma2(ull a, ull b, ull c) {
    ull d;
    asm("fma.rn.f32x2 %0, %1, %2, %3;" : "=l"(d) : "l"(a), "l"(b), "l"(c));
    return d;
}
__device__ __forceinline__ ull pk2(float lo, float hi) {
    ull r;
    asm("mov.b64 %0, {%1, %2};" : "=l"(r) : "f"(lo), "f"(hi));
    return r;
}
__device__ __forceinline__ float2 unpk2(ull v) {
    float2 r;
    asm("mov.b64 {%0, %1}, %2;" : "=f"(r.x), "=f"(r.y) : "l"(v));
    return r;
}

__global__ void reset_bar_kernel() {
    if (threadIdx.x < 64) g_bar[threadIdx.x] = 0u;
}

// ---------------- GEMM: C[M,N] = A(M,K) * Bw(N,K)^T + bias(N) ----------------
// 128x128 tile, 16-k, 256 threads, 8x8 microtile via FFMA2, global->reg prefetch.
#define GBM 128
#define GBN 128
#define GBK 16

template <bool GATHER>
__global__ void __launch_bounds__(256)
gemm_nt_bias(const float* __restrict__ A, const int* __restrict__ textp,
             const float* __restrict__ Bw, const float* __restrict__ bias,
             float* __restrict__ C, int M, int N, int Kd, int lda)
{
    __shared__ float As[GBK * GBM];
    __shared__ float Bs[GBK * GBN];

    const int tid = threadIdx.x;
    const int m0  = blockIdx.y * GBM;
    const int n0  = blockIdx.x * GBN;
    const int tx  = tid & 15;
    const int ty  = tid >> 4;
    const int lrow = tid >> 1;
    const int lkv0 = (tid & 1) * 2;

    ull acc2[8][4];
    #pragma unroll
    for (int i = 0; i < 8; ++i)
        #pragma unroll
        for (int j = 0; j < 4; ++j) acc2[i][j] = 0ull;

    const float* arow_p;
    {
        const int m = m0 + lrow;
        if (GATHER) {
            const int bb = m & 63;
            const int tt = m >> 6;
            const int tok = textp[bb * TQ + tt];
            arow_p = A + (size_t)tok * lda;
        } else {
            arow_p = A + (size_t)m * lda;
        }
    }
    const int nrow = n0 + lrow;
    const float* brow_p = Bw + (size_t)nrow * Kd;
    const bool bvalid = nrow < N;

    const int Ktiles = (Kd + GBK - 1) / GBK;

    float4 cva[2], cvb[2], nva[2], nvb[2];
    #pragma unroll
    for (int q = 0; q < 2; ++q) {
        const int kg = (lkv0 + q) * 4;
        cva[q] = make_float4(0.f, 0.f, 0.f, 0.f);
        cvb[q] = make_float4(0.f, 0.f, 0.f, 0.f);
        if (kg + 3 < Kd) {
            cva[q] = *(const float4*)(arow_p + kg);
            if (bvalid) cvb[q] = *(const float4*)(brow_p + kg);
        }
    }

    for (int kt = 0; kt < Ktiles; ++kt) {
        __syncthreads();
        #pragma unroll
        for (int q = 0; q < 2; ++q) {
            const int kv = lkv0 + q;
            As[(kv * 4 + 0) * GBM + lrow] = cva[q].x;
            As[(kv * 4 + 1) * GBM + lrow] = cva[q].y;
            As[(kv * 4 + 2) * GBM + lrow] = cva[q].z;
            As[(kv * 4 + 3) * GBM + lrow] = cva[q].w;
            Bs[(kv * 4 + 0) * GBN + lrow] = cvb[q].x;
            Bs[(kv * 4 + 1) * GBN + lrow] = cvb[q].y;
            Bs[(kv * 4 + 2) * GBN + lrow] = cvb[q].z;
            Bs[(kv * 4 + 3) * GBN + lrow] = cvb[q].w;
        }
        __syncthreads();
        if (kt + 1 < Ktiles) {
            #pragma unroll
            for (int q = 0; q < 2; ++q) {
                const int kg = (kt + 1) * GBK + (lkv0 + q) * 4;
                nva[q] = make_float4(0.f, 0.f, 0.f, 0.f);
                nvb[q] = make_float4(0.f, 0.f, 0.f, 0.f);
                if (kg + 3 < Kd) {
                    nva[q] = *(const float4*)(arow_p + kg);
                    if (bvalid) nvb[q] = *(const float4*)(brow_p + kg);
                }
            }
        }
        #pragma unroll
        for (int k = 0; k < GBK; ++k) {
            const float4 a0 = *(const float4*)&As[k * GBM + ty * 4];
            const float4 a1 = *(const float4*)&As[k * GBM + 64 + ty * 4];
            const ulonglong2 b0 = *(const ulonglong2*)&Bs[k * GBN + tx * 4];
            const ulonglong2 b1 = *(const ulonglong2*)&Bs[k * GBN + 64 + tx * 4];
            const ull bv2[4] = {b0.x, b0.y, b1.x, b1.y};
            const float av[8] = {a0.x, a0.y, a0.z, a0.w, a1.x, a1.y, a1.z, a1.w};
            #pragma unroll
            for (int i = 0; i < 8; ++i) {
                const ull av2 = pk2(av[i], av[i]);
                #pragma unroll
                for (int j = 0; j < 4; ++j)
                    acc2[i][j] = ffma2(av2, bv2[j], acc2[i][j]);
            }
        }
        #pragma unroll
        for (int q = 0; q < 2; ++q) { cva[q] = nva[q]; cvb[q] = nvb[q]; }
    }
    #pragma unroll
    for (int i = 0; i < 8; ++i) {
        const int mi = (i < 4) ? (ty * 4 + i) : (64 + ty * 4 + (i - 4));
        const int m  = m0 + mi;
        #pragma unroll
        for (int j = 0; j < 4; ++j) {
            const float2 v = unpk2(acc2[i][j]);
            const int c0 = (j < 2) ? (tx * 4 + 2 * j) : (64 + tx * 4 + 2 * (j - 2));
            if (c0 + 0 + n0 < N) C[(size_t)m * N + n0 + c0 + 0] = v.x + bias[n0 + c0 + 0];
            if (c0 + 1 + n0 < N) C[(size_t)m * N + n0 + c0 + 1] = v.y + bias[n0 + c0 + 1];
        }
    }
}

// ---------------- persistent bidirectional LSTM scan ----------------
// grid = 128 blocks: [0,64) fwd, [64,128) bwd. 256 threads.
// Block owns 4 hidden units x 64 batches; Whh slice in SMEM (R6 structure).
// Thread map: bgrp=tid>>5 (8 batches), u=(tid>>3)&3 (unit), ks=tid&7 (k-slice).
// Value-routed butterfly: lane ks ends up owning batch bgrp*8+ks -> parallel epilogue.
// Inter-CTA sync: single atomic counter per direction (PROVEN in R6).
#define LSTM_SMEM (64 * 65 * 16 + 16 * 264 * 4)   // hs float4[64][65] + Ws[16][264]

__global__ void __launch_bounds__(256)
lstm_scan(const float* __restrict__ xgF, const float* __restrict__ xgBk,
          const float* __restrict__ WhhF, const float* __restrict__ WhhB,
          float* __restrict__ hout)
{
    extern __shared__ char sm_raw[];
    float4* hs = (float4*)sm_raw;                     // [64][65]
    float*  Ws = (float*)(sm_raw + 64 * 65 * 16);     // [16][264]

    const int dir = blockIdx.x >> 6;
    const int blk = blockIdx.x & 63;
    const int u0  = blk * 4;
    const int tid = threadIdx.x;
    const int bgrp = tid >> 5;        // 0..7 -> batches bgrp*8 .. +7
    const int u    = (tid >> 3) & 3;
    const int ks   = tid & 7;
    const int unit = u0 + u;
    const int dof  = dir ? 256 : 0;
    const int bb   = bgrp * 8 + ks;   // this thread's epilogue batch

    const float* xg  = dir ? xgBk : xgF;
    const float* Whh = dir ? WhhB : WhhF;
    unsigned* bar = &g_bar[dir * 32];

    for (int i = tid; i < 16 * 256; i += 256) {
        const int r = i >> 8, k = i & 255;
        const int g = r >> 2, uu = r & 3;
        Ws[r * 264 + k] = Whh[(size_t)(g * 256 + u0 + uu) * 256 + k];
    }
    __syncthreads();

    const float4* wp0 = (const float4*)&Ws[(0 * 4 + u) * 264];
    const float4* wp1 = (const float4*)&Ws[(1 * 4 + u) * 264];
    const float4* wp2 = (const float4*)&Ws[(2 * 4 + u) * 264];
    const float4* wp3 = (const float4*)&Ws[(3 * 4 + u) * 264];

    float cc = 0.0f;

    for (int s = 0; s < TQ; ++s) {
        const int t = dir ? (TQ - 1 - s) : s;

        // xg prefetch: every thread loads the 4 gate inputs for ITS batch/unit
        const float* xr = xg + ((size_t)t * BQ + bb) * 1024 + unit;
        const float xv0 = __ldg(xr + 0);
        const float xv1 = __ldg(xr + 256);
        const float xv2 = __ldg(xr + 512);
        const float xv3 = __ldg(xr + 768);

        ull acc2[8][4];
        #pragma unroll
        for (int i = 0; i < 8; ++i)
            #pragma unroll
            for (int g = 0; g < 4; ++g) acc2[i][g] = 0ull;

        if (s > 0) {
            // stage h_prev (64 x 256 of this direction) into smem, coalesced
            const int tp = dir ? (t + 1) : (t - 1);
            const float* hb = hout + (size_t)tp * BQ * 512 + dof;
            #pragma unroll
            for (int j = 0; j < 16; ++j) {
                const int idx = tid + j * 256;
                const int b = idx >> 6, kv = idx & 63;
                hs[b * 65 + kv] = __ldg((const float4*)(hb + (size_t)b * 512 + kv * 4));
            }
            __syncthreads();
            // mat-vec from smem, k-pairs in f32x2 lanes
            #pragma unroll
            for (int q = 0; q < 8; ++q) {
                const int kv = ks + q * 8;
                const ulonglong2 w0 = *(const ulonglong2*)(wp0 + kv);
                const ulonglong2 w1 = *(const ulonglong2*)(wp1 + kv);
                const ulonglong2 w2 = *(const ulonglong2*)(wp2 + kv);
                const ulonglong2 w3 = *(const ulonglong2*)(wp3 + kv);
                #pragma unroll
                for (int i = 0; i < 8; ++i) {
                    const ulonglong2 h2 = *(const ulonglong2*)&hs[(bgrp * 8 + i) * 65 + kv];
                    acc2[i][0] = ffma2(h2.x, w0.x, acc2[i][0]);
                    acc2[i][0] = ffma2(h2.y, w0.y, acc2[i][0]);
                    acc2[i][1] = ffma2(h2.x, w1.x, acc2[i][1]);
                    acc2[i][1] = ffma2(h2.y, w1.y, acc2[i][1]);
                    acc2[i][2] = ffma2(h2.x, w2.x, acc2[i][2]);
                    acc2[i][2] = ffma2(h2.y, w2.y, acc2[i][2]);
                    acc2[i][3] = ffma2(h2.x, w3.x, acc2[i][3]);
                    acc2[i][3] = ffma2(h2.y, w3.y, acc2[i][3]);
                }
            }
        }

        // ---- value-routed butterfly over ks lanes ----
        float v8[8][4];
        #pragma unroll
        for (int i = 0; i < 8; ++i)
            #pragma unroll
            for (int g = 0; g < 4; ++g) {
                const float2 p = unpk2(acc2[i][g]);
                v8[i][g] = p.x + p.y;
            }
        const bool q2 = (ks & 4) != 0;
        float v4[4][4];
        #pragma unroll
        for (int j = 0; j < 4; ++j)
            #pragma unroll
            for (int g = 0; g < 4; ++g) {
                const float snd = q2 ? v8[j][g] : v8[j + 4][g];
                const float got = __shfl_xor_sync(0xffffffffu, snd, 4);
                v4[j][g] = (q2 ? v8[j + 4][g] : v8[j][g]) + got;
            }
        const bool q1 = (ks & 2) != 0;
        float v2r[2][4];
        #pragma unroll
        for (int j = 0; j < 2; ++j)
            #pragma unroll
            for (int g = 0; g < 4; ++g) {
                const float snd = q1 ? v4[j][g] : v4[j + 2][g];
                const float got = __shfl_xor_sync(0xffffffffu, snd, 2);
                v2r[j][g] = (q1 ? v4[j + 2][g] : v4[j][g]) + got;
            }
        const bool q0 = (ks & 1) != 0;
        float z[4];
        #pragma unroll
        for (int g = 0; g < 4; ++g) {
            const float snd = q0 ? v2r[0][g] : v2r[1][g];
            const float got = __shfl_xor_sync(0xffffffffu, snd, 1);
            z[g] = (q0 ? v2r[1][g] : v2r[0][g]) + got;
        }

        // ---- fully parallel epilogue: one LSTM cell per thread ----
        {
            const float zi = z[0] + xv0;
            const float zf = z[1] + xv1;
            const float zg = z[2] + xv2;
            const float zo = z[3] + xv3;
            const float ig = sigf(zi), fg = sigf(zf), gg = tanh_f(zg), og = sigf(zo);
            cc = fg * cc + ig * gg;
            hout[((size_t)t * BQ + bb) * 512 + dof + unit] = og * tanh_f(cc);
        }

        // ---- inter-CTA step barrier: single atomic counter (R6-proven) ----
        if (s + 1 < TQ) {
            __threadfence();
            __syncthreads();
            if (tid == 0) {
                atomicAdd(bar, 1u);
                const unsigned target = (unsigned)(s + 1) * 64u;
                while (*((volatile unsigned*)bar) < target) { }
            }
            __syncthreads();
        }
    }
}

// ---------------- CRF: one block per batch ----------------
__global__ void __launch_bounds__(64)
crf_kernel(const int* __restrict__ text, const int* __restrict__ sbj,
           const float* __restrict__ em, const float* __restrict__ start_t,
           const float* __restrict__ end_t, const float* __restrict__ trans,
           float* __restrict__ llh)
{
    const int b   = blockIdx.x;
    const int tid = threadIdx.x;
    __shared__ float tr[KQ * KQ];
    __shared__ float sc[KQ];
    for (int i = tid; i < KQ * KQ; i += 64) tr[i] = trans[i];
    if (tid < KQ) sc[tid] = start_t[tid] + em[(size_t)b * KQ + tid];
    __syncthreads();

    for (int t = 1; t < TQ; ++t) {
        const int tok = text[b * TQ + t];
        if (tok != 0) {
            float nv = 0.0f;
            if (tid < KQ) {
                float mx = -1e30f;
                #pragma unroll 1
                for (int j = 0; j < KQ; ++j) mx = fmaxf(mx, sc[j] + tr[j * KQ + tid]);
                float ssum = 0.0f;
                #pragma unroll 1
                for (int j = 0; j < KQ; ++j) ssum += __expf(sc[j] + tr[j * KQ + tid] - mx);
                nv = em[((size_t)t * BQ + b) * KQ + tid] + mx + __logf(ssum);
            }
            __syncthreads();
            if (tid < KQ) sc[tid] = nv;
            __syncthreads();
        }
    }

    if (tid == 0) {
        float mx = -1e30f;
        for (int k = 0; k < KQ; ++k) mx = fmaxf(mx, sc[k] + end_t[k]);
        float ssum = 0.0f;
        for (int k = 0; k < KQ; ++k) ssum += __expf(sc[k] + end_t[k] - mx);
        const float logZ = mx + __logf(ssum);
        int tag0 = sbj[b * TQ + 0];
        float num = start_t[tag0] + em[(size_t)b * KQ + tag0];
        int prev = tag0, last = tag0;
        for (int t = 1; t < TQ; ++t) {
            if (text[b * TQ + t] != 0) {
                const int tg = sbj[b * TQ + t];
                num += em[((size_t)t * BQ + b) * KQ + tg] + tr[prev * KQ + tg];
                prev = tg; last = tg;
            }
        }
        num += end_t[last];
        llh[b] = num - logZ;
    }
}

// ---------------- finalize ----------------
__global__ void __launch_bounds__(256)
finalize_kernel(const int* __restrict__ text, const float* __restrict__ llh,
                float* __restrict__ out)
{
    __shared__ float sred[256];
    __shared__ float cred[256];
    const int tid = threadIdx.x;
    float s = 0.0f, c = 0.0f;
    for (int i = tid; i < BQ; i += 256) s += llh[i];
    for (int i = tid; i < BQ * TQ; i += 256) c += (text[i] != 0) ? 1.0f : 0.0f;
    sred[tid] = s; cred[tid] = c;
    __syncthreads();
    for (int off = 128; off > 0; off >>= 1) {
        if (tid < off) { sred[tid] += sred[tid + off]; cred[tid] += cred[tid + off]; }
        __syncthreads();
    }
    if (tid == 0) out[0] = -(sred[0] / cred[0]);
}

// ---------------- launch ----------------
extern "C" void kernel_launch(void* const* d_in, const int* in_sizes, int n_in,
                              void* d_out, int out_size)
{
    const int*   text  = (const int*)  d_in[0];
    const int*   sbj   = (const int*)  d_in[1];
    const float* emb   = (const float*)d_in[2];
    const float* Wih0f = (const float*)d_in[3];
    const float* Whh0f = (const float*)d_in[4];
    const float* b0f   = (const float*)d_in[5];
    const float* Wih0b = (const float*)d_in[6];
    const float* Whh0b = (const float*)d_in[7];
    const float* b0b   = (const float*)d_in[8];
    const float* Wih1f = (const float*)d_in[9];
    const float* Whh1f = (const float*)d_in[10];
    const float* b1f   = (const float*)d_in[11];
    const float* Wih1b = (const float*)d_in[12];
    const float* Whh1b = (const float*)d_in[13];
    const float* b1b   = (const float*)d_in[14];
    const float* W_sbj = (const float*)d_in[15];
    const float* b_sbj = (const float*)d_in[16];
    const float* st_t  = (const float*)d_in[17];
    const float* en_t  = (const float*)d_in[18];
    const float* trans = (const float*)d_in[19];
    float* out = (float*)d_out;

    float *xgA, *xgB, *h0, *h1, *em, *llh;
    cudaGetSymbolAddress((void**)&xgA, g_xgA);
    cudaGetSymbolAddress((void**)&xgB, g_xgB);
    cudaGetSymbolAddress((void**)&h0,  g_h0);
    cudaGetSymbolAddress((void**)&h1,  g_h1);
    cudaGetSymbolAddress((void**)&em,  g_em);
    cudaGetSymbolAddress((void**)&llh, g_llh);

    cudaFuncSetAttribute(lstm_scan, cudaFuncAttributeMaxDynamicSharedMemorySize, LSTM_SMEM);

    const dim3 gGemmFull(1024 / GBN, MBQ / GBM);   // (8, 128)
    const dim3 gGemmEm(1, MBQ / GBM);              // (1, 128)  N=37

    gemm_nt_bias<true><<<gGemmFull, 256>>>(emb, text, Wih0f, b0f, xgA, MBQ, 1024, DQ, DQ);
    gemm_nt_bias<true><<<gGemmFull, 256>>>(emb, text, Wih0b, b0b, xgB, MBQ, 1024, DQ, DQ);
    reset_bar_kernel<<<1, 64>>>();
    lstm_scan<<<128, 256, LSTM_SMEM>>>(xgA, xgB, Whh0f, Whh0b, h0);

    gemm_nt_bias<false><<<gGemmFull, 256>>>(h0, nullptr, Wih1f, b1f, xgA, MBQ, 1024, 512, 512);
    gemm_nt_bias<false><<<gGemmFull, 256>>>(h0, nullptr, Wih1b, b1b, xgB, MBQ, 1024, 512, 512);
    reset_bar_kernel<<<1, 64>>>();
    lstm_scan<<<128, 256, LSTM_SMEM>>>(xgA, xgB, Whh1f, Whh1b, h1);

    gemm_nt_bias<false><<<gGemmEm, 256>>>(h1, nullptr, W_sbj, b_sbj, em, MBQ, KQ, 512, 512);

    crf_kernel<<<BQ, 64>>>(text, sbj, em, st_t, en_t, trans, llh);
    finalize_kernel<<<1, 256>>>(text, llh, out);
}

// round 12
// speedup vs baseline: 2.0289x; 1.0380x over previous
#include <cuda_runtime.h>
#include <cstdint>

// Problem dims (fixed for this instance)
#define BQ 64
#define TQ 256
#define DQ 300
#define HQ 256      // hidden
#define KQ 37       // tags
#define MBQ (TQ*BQ) // 16384 rows (t*B + b)

typedef unsigned long long ull;

// ---------------- scratch (static device globals; no allocation) ----------------
__device__ float g_xgA[(size_t)MBQ * 1024];  // 64 MB (gate-interleaved [t][b][unit][gate])
__device__ float g_xgB[(size_t)MBQ * 1024];  // 64 MB
__device__ float g_h0 [(size_t)MBQ * 512];   // 32 MB
__device__ float g_h1 [(size_t)MBQ * 512];   // 32 MB
__device__ float g_em [(size_t)MBQ * KQ];    // 2.4 MB
__device__ float g_llh[BQ];
__device__ unsigned g_bar[512];              // 16 used counters, padded 128B apart

// ---------------- helpers ----------------
__device__ __forceinline__ float sigf(float x)   { return 1.0f / (1.0f + __expf(-x)); }
__device__ __forceinline__ float tanh_f(float x) { return 2.0f / (1.0f + __expf(-2.0f * x)) - 1.0f; }

__device__ __forceinline__ ull ffma2(ull a, ull b, ull c) {
    ull d;
    asm("fma.rn.f32x2 %0, %1, %2, %3;" : "=l"(d) : "l"(a), "l"(b), "l"(c));
    return d;
}
__device__ __forceinline__ ull pk2(float lo, float hi) {
    ull r;
    asm("mov.b64 %0, {%1, %2};" : "=l"(r) : "f"(lo), "f"(hi));
    return r;
}
__device__ __forceinline__ float2 unpk2(ull v) {
    float2 r;
    asm("mov.b64 {%0, %1}, %2;" : "=f"(r.x), "=f"(r.y) : "l"(v));
    return r;
}

__global__ void reset_bar_kernel() {
    if (threadIdx.x < 512) g_bar[threadIdx.x] = 0u;
}

// ---------------- GEMM: C[M,N] = A(M,K) * Bw(N,K)^T + bias(N) ----------------
// 128x128 tile, 16-k, 256 threads, 8x8 microtile via FFMA2, global->reg prefetch.
// XGI: write column (n&255)*4 + (n>>8) instead of n (gate-interleaved xg layout).
#define GBM 128
#define GBN 128
#define GBK 16

template <bool GATHER, bool XGI>
__global__ void __launch_bounds__(256)
gemm_nt_bias(const float* __restrict__ A, const int* __restrict__ textp,
             const float* __restrict__ Bw, const float* __restrict__ bias,
             float* __restrict__ C, int M, int N, int Kd, int lda)
{
    __shared__ float As[GBK * GBM];
    __shared__ float Bs[GBK * GBN];

    const int tid = threadIdx.x;
    const int m0  = blockIdx.y * GBM;
    const int n0  = blockIdx.x * GBN;
    const int tx  = tid & 15;
    const int ty  = tid >> 4;
    const int lrow = tid >> 1;
    const int lkv0 = (tid & 1) * 2;

    ull acc2[8][4];
    #pragma unroll
    for (int i = 0; i < 8; ++i)
        #pragma unroll
        for (int j = 0; j < 4; ++j) acc2[i][j] = 0ull;

    const float* arow_p;
    {
        const int m = m0 + lrow;
        if (GATHER) {
            const int bb = m & 63;
            const int tt = m >> 6;
            const int tok = textp[bb * TQ + tt];
            arow_p = A + (size_t)tok * lda;
        } else {
            arow_p = A + (size_t)m * lda;
        }
    }
    const int nrow = n0 + lrow;
    const float* brow_p = Bw + (size_t)nrow * Kd;
    const bool bvalid = nrow < N;

    const int Ktiles = (Kd + GBK - 1) / GBK;

    float4 cva[2], cvb[2], nva[2], nvb[2];
    #pragma unroll
    for (int q = 0; q < 2; ++q) {
        const int kg = (lkv0 + q) * 4;
        cva[q] = make_float4(0.f, 0.f, 0.f, 0.f);
        cvb[q] = make_float4(0.f, 0.f, 0.f, 0.f);
        if (kg + 3 < Kd) {
            cva[q] = *(const float4*)(arow_p + kg);
            if (bvalid) cvb[q] = *(const float4*)(brow_p + kg);
        }
    }

    for (int kt = 0; kt < Ktiles; ++kt) {
        __syncthreads();
        #pragma unroll
        for (int q = 0; q < 2; ++q) {
            const int kv = lkv0 + q;
            As[(kv * 4 + 0) * GBM + lrow] = cva[q].x;
            As[(kv * 4 + 1) * GBM + lrow] = cva[q].y;
            As[(kv * 4 + 2) * GBM + lrow] = cva[q].z;
            As[(kv * 4 + 3) * GBM + lrow] = cva[q].w;
            Bs[(kv * 4 + 0) * GBN + lrow] = cvb[q].x;
            Bs[(kv * 4 + 1) * GBN + lrow] = cvb[q].y;
            Bs[(kv * 4 + 2) * GBN + lrow] = cvb[q].z;
            Bs[(kv * 4 + 3) * GBN + lrow] = cvb[q].w;
        }
        __syncthreads();
        if (kt + 1 < Ktiles) {
            #pragma unroll
            for (int q = 0; q < 2; ++q) {
                const int kg = (kt + 1) * GBK + (lkv0 + q) * 4;
                nva[q] = make_float4(0.f, 0.f, 0.f, 0.f);
                nvb[q] = make_float4(0.f, 0.f, 0.f, 0.f);
                if (kg + 3 < Kd) {
                    nva[q] = *(const float4*)(arow_p + kg);
                    if (bvalid) nvb[q] = *(const float4*)(brow_p + kg);
                }
            }
        }
        #pragma unroll
        for (int k = 0; k < GBK; ++k) {
            const float4 a0 = *(const float4*)&As[k * GBM + ty * 4];
            const float4 a1 = *(const float4*)&As[k * GBM + 64 + ty * 4];
            const ulonglong2 b0 = *(const ulonglong2*)&Bs[k * GBN + tx * 4];
            const ulonglong2 b1 = *(const ulonglong2*)&Bs[k * GBN + 64 + tx * 4];
            const ull bv2[4] = {b0.x, b0.y, b1.x, b1.y};
            const float av[8] = {a0.x, a0.y, a0.z, a0.w, a1.x, a1.y, a1.z, a1.w};
            #pragma unroll
            for (int i = 0; i < 8; ++i) {
                const ull av2 = pk2(av[i], av[i]);
                #pragma unroll
                for (int j = 0; j < 4; ++j)
                    acc2[i][j] = ffma2(av2, bv2[j], acc2[i][j]);
            }
        }
        #pragma unroll
        for (int q = 0; q < 2; ++q) { cva[q] = nva[q]; cvb[q] = nvb[q]; }
    }
    #pragma unroll
    for (int i = 0; i < 8; ++i) {
        const int mi = (i < 4) ? (ty * 4 + i) : (64 + ty * 4 + (i - 4));
        const int m  = m0 + mi;
        #pragma unroll
        for (int j = 0; j < 4; ++j) {
            const float2 v = unpk2(acc2[i][j]);
            const int c0 = (j < 2) ? (tx * 4 + 2 * j) : (64 + tx * 4 + 2 * (j - 2));
            const int n1 = n0 + c0, n2 = n0 + c0 + 1;
            if (XGI) {
                C[(size_t)m * N + ((n1 & 255) * 4 + (n1 >> 8))] = v.x + bias[n1];
                C[(size_t)m * N + ((n2 & 255) * 4 + (n2 >> 8))] = v.y + bias[n2];
            } else {
                if (n1 < N) C[(size_t)m * N + n1] = v.x + bias[n1];
                if (n2 < N) C[(size_t)m * N + n2] = v.y + bias[n2];
            }
        }
    }
}

// ---------------- persistent bidirectional LSTM scan ----------------
// grid = 128 blocks = 2 dirs x 8 batch-groups x 8 unit-slices.
// CTA owns 8 batches x 32 units (all 4 gates); Whh slice (128 rows x 256) in smem.
// Thread map: ul=tid>>3 (local unit 0..31), ks=tid&7 (k-slice AND epilogue batch).
// Barrier only spans the 8 CTAs sharing a batch-group (single atomic counter each).
#define LSTM_SMEM (8 * 65 * 16 + 128 * 264 * 4)   // hs float4[8][65] + Ws[128][264]

__global__ void __launch_bounds__(256)
lstm_scan(const float* __restrict__ xgF, const float* __restrict__ xgBk,
          const float* __restrict__ WhhF, const float* __restrict__ WhhB,
          float* __restrict__ hout)
{
    extern __shared__ char sm_raw[];
    float4* hs = (float4*)sm_raw;                    // [8][65]
    float*  Ws = (float*)(sm_raw + 8 * 65 * 16);     // [128][264]

    const int dir = blockIdx.x >> 6;
    const int loc = blockIdx.x & 63;
    const int bg  = loc >> 3;         // batch group 0..7
    const int us  = loc & 7;          // unit slice 0..7
    const int b0  = bg * 8;
    const int u0  = us * 32;
    const int tid = threadIdx.x;
    const int ul  = tid >> 3;         // local unit 0..31
    const int ks  = tid & 7;          // k-slice / epilogue batch
    const int unit = u0 + ul;
    const int dof  = dir ? 256 : 0;
    const int bb   = b0 + ks;         // this thread's epilogue batch

    const float* xg  = dir ? xgBk : xgF;
    const float* Whh = dir ? WhhB : WhhF;
    unsigned* bar = &g_bar[(dir * 8 + bg) * 32];

    // load Whh slice: rows r = g*32 + ul_local, cols k
    for (int i = tid; i < 128 * 256; i += 256) {
        const int r = i >> 8, k = i & 255;
        const int g = r >> 5, uu = r & 31;
        Ws[r * 264 + k] = Whh[(size_t)(g * 256 + u0 + uu) * 256 + k];
    }
    __syncthreads();

    const float4* wp0 = (const float4*)&Ws[(0 * 32 + ul) * 264];
    const float4* wp1 = (const float4*)&Ws[(1 * 32 + ul) * 264];
    const float4* wp2 = (const float4*)&Ws[(2 * 32 + ul) * 264];
    const float4* wp3 = (const float4*)&Ws[(3 * 32 + ul) * 264];

    float cc = 0.0f;

    for (int s = 0; s < TQ; ++s) {
        const int t = dir ? (TQ - 1 - s) : s;

        // xg prefetch: ONE float4 = 4 gate inputs for (bb, unit) (interleaved layout)
        const float4 xq = __ldg((const float4*)(xg + ((size_t)t * BQ + bb) * 1024 + (size_t)unit * 4));

        ull acc2[8][4];
        #pragma unroll
        for (int i = 0; i < 8; ++i)
            #pragma unroll
            for (int g = 0; g < 4; ++g) acc2[i][g] = 0ull;

        if (s > 0) {
            // stage h_prev for OUR 8 batches (this direction) into smem, coalesced
            const int tp = dir ? (t + 1) : (t - 1);
            const float* hb = hout + ((size_t)tp * BQ + b0) * 512 + dof;
            #pragma unroll
            for (int j = 0; j < 2; ++j) {
                const int idx = tid + j * 256;
                const int b = idx >> 6, kv = idx & 63;
                hs[b * 65 + kv] = __ldg((const float4*)(hb + (size_t)b * 512 + kv * 4));
            }
            __syncthreads();
            // mat-vec from smem, k-pairs in f32x2 lanes
            #pragma unroll
            for (int q = 0; q < 8; ++q) {
                const int kv = ks + q * 8;
                const ulonglong2 w0 = *(const ulonglong2*)(wp0 + kv);
                const ulonglong2 w1 = *(const ulonglong2*)(wp1 + kv);
                const ulonglong2 w2 = *(const ulonglong2*)(wp2 + kv);
                const ulonglong2 w3 = *(const ulonglong2*)(wp3 + kv);
                #pragma unroll
                for (int i = 0; i < 8; ++i) {
                    const ulonglong2 h2 = *(const ulonglong2*)&hs[i * 65 + kv];
                    acc2[i][0] = ffma2(h2.x, w0.x, acc2[i][0]);
                    acc2[i][0] = ffma2(h2.y, w0.y, acc2[i][0]);
                    acc2[i][1] = ffma2(h2.x, w1.x, acc2[i][1]);
                    acc2[i][1] = ffma2(h2.y, w1.y, acc2[i][1]);
                    acc2[i][2] = ffma2(h2.x, w2.x, acc2[i][2]);
                    acc2[i][2] = ffma2(h2.y, w2.y, acc2[i][2]);
                    acc2[i][3] = ffma2(h2.x, w3.x, acc2[i][3]);
                    acc2[i][3] = ffma2(h2.y, w3.y, acc2[i][3]);
                }
            }
        }

        // ---- value-routed butterfly over ks lanes: lane ks ends owning batch ks ----
        float v8[8][4];
        #pragma unroll
        for (int i = 0; i < 8; ++i)
            #pragma unroll
            for (int g = 0; g < 4; ++g) {
                const float2 p = unpk2(acc2[i][g]);
                v8[i][g] = p.x + p.y;
            }
        const bool q2 = (ks & 4) != 0;
        float v4[4][4];
        #pragma unroll
        for (int j = 0; j < 4; ++j)
            #pragma unroll
            for (int g = 0; g < 4; ++g) {
                const float snd = q2 ? v8[j][g] : v8[j + 4][g];
                const float got = __shfl_xor_sync(0xffffffffu, snd, 4);
                v4[j][g] = (q2 ? v8[j + 4][g] : v8[j][g]) + got;
            }
        const bool q1 = (ks & 2) != 0;
        float v2r[2][4];
        #pragma unroll
        for (int j = 0; j < 2; ++j)
            #pragma unroll
            for (int g = 0; g < 4; ++g) {
                const float snd = q1 ? v4[j][g] : v4[j + 2][g];
                const float got = __shfl_xor_sync(0xffffffffu, snd, 2);
                v2r[j][g] = (q1 ? v4[j + 2][g] : v4[j][g]) + got;
            }
        const bool q0 = (ks & 1) != 0;
        float z[4];
        #pragma unroll
        for (int g = 0; g < 4; ++g) {
            const float snd = q0 ? v2r[0][g] : v2r[1][g];
            const float got = __shfl_xor_sync(0xffffffffu, snd, 1);
            z[g] = (q0 ? v2r[1][g] : v2r[0][g]) + got;
        }

        // ---- fully parallel epilogue: one LSTM cell per thread ----
        {
            const float zi = z[0] + xq.x;
            const float zf = z[1] + xq.y;
            const float zg = z[2] + xq.z;
            const float zo = z[3] + xq.w;
            const float ig = sigf(zi), fg = sigf(zf), gg = tanh_f(zg), og = sigf(zo);
            cc = fg * cc + ig * gg;
            hout[((size_t)t * BQ + bb) * 512 + dof + unit] = og * tanh_f(cc);
        }

        // ---- inter-CTA step barrier: spans only the 8 CTAs of this batch-group ----
        if (s + 1 < TQ) {
            __threadfence();
            __syncthreads();
            if (tid == 0) {
                atomicAdd(bar, 1u);
                const unsigned target = (unsigned)(s + 1) * 8u;
                while (*((volatile unsigned*)bar) < target) { }
            }
            __syncthreads();
        }
    }
}

// ---------------- CRF: one block per batch ----------------
__global__ void __launch_bounds__(64)
crf_kernel(const int* __restrict__ text, const int* __restrict__ sbj,
           const float* __restrict__ em, const float* __restrict__ start_t,
           const float* __restrict__ end_t, const float* __restrict__ trans,
           float* __restrict__ llh)
{
    const int b   = blockIdx.x;
    const int tid = threadIdx.x;
    __shared__ float tr[KQ * KQ];
    __shared__ float sc[KQ];
    for (int i = tid; i < KQ * KQ; i += 64) tr[i] = trans[i];
    if (tid < KQ) sc[tid] = start_t[tid] + em[(size_t)b * KQ + tid];
    __syncthreads();

    for (int t = 1; t < TQ; ++t) {
        const int tok = text[b * TQ + t];
        if (tok != 0) {
            float nv = 0.0f;
            if (tid < KQ) {
                float mx = -1e30f;
                #pragma unroll 1
                for (int j = 0; j < KQ; ++j) mx = fmaxf(mx, sc[j] + tr[j * KQ + tid]);
                float ssum = 0.0f;
                #pragma unroll 1
                for (int j = 0; j < KQ; ++j) ssum += __expf(sc[j] + tr[j * KQ + tid] - mx);
                nv = em[((size_t)t * BQ + b) * KQ + tid] + mx + __logf(ssum);
            }
            __syncthreads();
            if (tid < KQ) sc[tid] = nv;
            __syncthreads();
        }
    }

    if (tid == 0) {
        float mx = -1e30f;
        for (int k = 0; k < KQ; ++k) mx = fmaxf(mx, sc[k] + end_t[k]);
        float ssum = 0.0f;
        for (int k = 0; k < KQ; ++k) ssum += __expf(sc[k] + end_t[k] - mx);
        const float logZ = mx + __logf(ssum);
        int tag0 = sbj[b * TQ + 0];
        float num = start_t[tag0] + em[(size_t)b * KQ + tag0];
        int prev = tag0, last = tag0;
        for (int t = 1; t < TQ; ++t) {
            if (text[b * TQ + t] != 0) {
                const int tg = sbj[b * TQ + t];
                num += em[((size_t)t * BQ + b) * KQ + tg] + tr[prev * KQ + tg];
                prev = tg; last = tg;
            }
        }
        num += end_t[last];
        llh[b] = num - logZ;
    }
}

// ---------------- finalize ----------------
__global__ void __launch_bounds__(256)
finalize_kernel(const int* __restrict__ text, const float* __restrict__ llh,
                float* __restrict__ out)
{
    __shared__ float sred[256];
    __shared__ float cred[256];
    const int tid = threadIdx.x;
    float s = 0.0f, c = 0.0f;
    for (int i = tid; i < BQ; i += 256) s += llh[i];
    for (int i = tid; i < BQ * TQ; i += 256) c += (text[i] != 0) ? 1.0f : 0.0f;
    sred[tid] = s; cred[tid] = c;
    __syncthreads();
    for (int off = 128; off > 0; off >>= 1) {
        if (tid < off) { sred[tid] += sred[tid + off]; cred[tid] += cred[tid + off]; }
        __syncthreads();
    }
    if (tid == 0) out[0] = -(sred[0] / cred[0]);
}

// ---------------- launch ----------------
extern "C" void kernel_launch(void* const* d_in, const int* in_sizes, int n_in,
                              void* d_out, int out_size)
{
    const int*   text  = (const int*)  d_in[0];
    const int*   sbj   = (const int*)  d_in[1];
    const float* emb   = (const float*)d_in[2];
    const float* Wih0f = (const float*)d_in[3];
    const float* Whh0f = (const float*)d_in[4];
    const float* b0f   = (const float*)d_in[5];
    const float* Wih0b = (const float*)d_in[6];
    const float* Whh0b = (const float*)d_in[7];
    const float* b0b   = (const float*)d_in[8];
    const float* Wih1f = (const float*)d_in[9];
    const float* Whh1f = (const float*)d_in[10];
    const float* b1f   = (const float*)d_in[11];
    const float* Wih1b = (const float*)d_in[12];
    const float* Whh1b = (const float*)d_in[13];
    const float* b1b   = (const float*)d_in[14];
    const float* W_sbj = (const float*)d_in[15];
    const float* b_sbj = (const float*)d_in[16];
    const float* st_t  = (const float*)d_in[17];
    const float* en_t  = (const float*)d_in[18];
    const float* trans = (const float*)d_in[19];
    float* out = (float*)d_out;

    float *xgA, *xgB, *h0, *h1, *em, *llh;
    cudaGetSymbolAddress((void**)&xgA, g_xgA);
    cudaGetSymbolAddress((void**)&xgB, g_xgB);
    cudaGetSymbolAddress((void**)&h0,  g_h0);
    cudaGetSymbolAddress((void**)&h1,  g_h1);
    cudaGetSymbolAddress((void**)&em,  g_em);
    cudaGetSymbolAddress((void**)&llh, g_llh);

    cudaFuncSetAttribute(lstm_scan, cudaFuncAttributeMaxDynamicSharedMemorySize, LSTM_SMEM);

    const dim3 gGemmFull(1024 / GBN, MBQ / GBM);   // (8, 128)
    const dim3 gGemmEm(1, MBQ / GBM);              // (1, 128)  N=37

    gemm_nt_bias<true, true><<<gGemmFull, 256>>>(emb, text, Wih0f, b0f, xgA, MBQ, 1024, DQ, DQ);
    gemm_nt_bias<true, true><<<gGemmFull, 256>>>(emb, text, Wih0b, b0b, xgB, MBQ, 1024, DQ, DQ);
    reset_bar_kernel<<<1, 512>>>();
    lstm_scan<<<128, 256, LSTM_SMEM>>>(xgA, xgB, Whh0f, Whh0b, h0);

    gemm_nt_bias<false, true><<<gGemmFull, 256>>>(h0, nullptr, Wih1f, b1f, xgA, MBQ, 1024, 512, 512);
    gemm_nt_bias<false, true><<<gGemmFull, 256>>>(h0, nullptr, Wih1b, b1b, xgB, MBQ, 1024, 512, 512);
    reset_bar_kernel<<<1, 512>>>();
    lstm_scan<<<128, 256, LSTM_SMEM>>>(xgA, xgB, Whh1f, Whh1b, h1);

    gemm_nt_bias<false, false><<<gGemmEm, 256>>>(h1, nullptr, W_sbj, b_sbj, em, MBQ, KQ, 512, 512);

    crf_kernel<<<BQ, 64>>>(text, sbj, em, st_t, en_t, trans, llh);
    finalize_kernel<<<1, 256>>>(text, llh, out);
}

// round 13
// speedup vs baseline: 2.1665x; 1.0678x over previous
#include <cuda_runtime.h>
#include <cstdint>

// Problem dims (fixed for this instance)
#define BQ 64
#define TQ 256
#define DQ 300
#define HQ 256      // hidden
#define KQ 37       // tags
#define MBQ (TQ*BQ) // 16384 rows (t*B + b)

typedef unsigned long long ull;

// ---------------- scratch (static device globals; no allocation) ----------------
__device__ float g_xgA[(size_t)MBQ * 1024];  // 64 MB (gate-interleaved [t][b][unit][gate])
__device__ float g_xgB[(size_t)MBQ * 1024];  // 64 MB
__device__ float g_h0 [(size_t)MBQ * 512];   // 32 MB
__device__ float g_h1 [(size_t)MBQ * 512];   // 32 MB
__device__ float g_em [(size_t)MBQ * KQ];    // 2.4 MB
__device__ float g_llh[BQ];
__device__ unsigned g_bar[512];              // 16 used counters, padded 128B apart

// ---------------- helpers ----------------
__device__ __forceinline__ float sigf(float x)   { return 1.0f / (1.0f + __expf(-x)); }
__device__ __forceinline__ float tanh_f(float x) { return 2.0f / (1.0f + __expf(-2.0f * x)) - 1.0f; }

__device__ __forceinline__ ull ffma2(ull a, ull b, ull c) {
    ull d;
    asm("fma.rn.f32x2 %0, %1, %2, %3;" : "=l"(d) : "l"(a), "l"(b), "l"(c));
    return d;
}
__device__ __forceinline__ ull pk2(float lo, float hi) {
    ull r;
    asm("mov.b64 %0, {%1, %2};" : "=l"(r) : "f"(lo), "f"(hi));
    return r;
}
__device__ __forceinline__ float2 unpk2(ull v) {
    float2 r;
    asm("mov.b64 {%0, %1}, %2;" : "=f"(r.x), "=f"(r.y) : "l"(v));
    return r;
}

__global__ void reset_bar_kernel() {
    if (threadIdx.x < 512) g_bar[threadIdx.x] = 0u;
}

// ---------------- GEMM: C[M,P] = A(M,K) * Bw'(P,K)^T + bias' ----------------
// 128x128 tile, 16-k, 256 threads, 8x8 microtile via FFMA2, reg prefetch,
// double-buffered smem (ONE sync per k-tile).
// XGI: logical output column p maps to weight/bias row (p&3)*256 + (p>>2)
//      (permutation applied at the B-LOAD, so C stores stay fully coalesced).
#define GBM 128
#define GBN 128
#define GBK 16

template <bool GATHER, bool XGI>
__global__ void __launch_bounds__(256)
gemm_nt_bias(const float* __restrict__ A, const int* __restrict__ textp,
             const float* __restrict__ Bw, const float* __restrict__ bias,
             float* __restrict__ C, int M, int N, int Kd, int lda)
{
    __shared__ float As[2][GBK * GBM];
    __shared__ float Bs[2][GBK * GBN];

    const int tid = threadIdx.x;
    const int m0  = blockIdx.y * GBM;
    const int n0  = blockIdx.x * GBN;
    const int tx  = tid & 15;
    const int ty  = tid >> 4;
    const int lrow = tid >> 1;
    const int lkv0 = (tid & 1) * 2;

    ull acc2[8][4];
    #pragma unroll
    for (int i = 0; i < 8; ++i)
        #pragma unroll
        for (int j = 0; j < 4; ++j) acc2[i][j] = 0ull;

    const float* arow_p;
    {
        const int m = m0 + lrow;
        if (GATHER) {
            const int bb = m & 63;
            const int tt = m >> 6;
            const int tok = textp[bb * TQ + tt];
            arow_p = A + (size_t)tok * lda;
        } else {
            arow_p = A + (size_t)m * lda;
        }
    }
    const int ncol = n0 + lrow;                                 // logical output col
    const int brow = XGI ? ((ncol & 3) * 256 + (ncol >> 2)) : ncol; // weight row
    const float* brow_p = Bw + (size_t)brow * Kd;
    const bool bvalid = ncol < N;

    const int Ktiles = (Kd + GBK - 1) / GBK;

    float4 cva[2], cvb[2], nva[2], nvb[2];
    #pragma unroll
    for (int q = 0; q < 2; ++q) {
        const int kg = (lkv0 + q) * 4;
        cva[q] = make_float4(0.f, 0.f, 0.f, 0.f);
        cvb[q] = make_float4(0.f, 0.f, 0.f, 0.f);
        if (kg + 3 < Kd) {
            cva[q] = *(const float4*)(arow_p + kg);
            if (bvalid) cvb[q] = *(const float4*)(brow_p + kg);
        }
    }

    for (int kt = 0; kt < Ktiles; ++kt) {
        const int pb = kt & 1;
        #pragma unroll
        for (int q = 0; q < 2; ++q) {
            const int kv = lkv0 + q;
            As[pb][(kv * 4 + 0) * GBM + lrow] = cva[q].x;
            As[pb][(kv * 4 + 1) * GBM + lrow] = cva[q].y;
            As[pb][(kv * 4 + 2) * GBM + lrow] = cva[q].z;
            As[pb][(kv * 4 + 3) * GBM + lrow] = cva[q].w;
            Bs[pb][(kv * 4 + 0) * GBN + lrow] = cvb[q].x;
            Bs[pb][(kv * 4 + 1) * GBN + lrow] = cvb[q].y;
            Bs[pb][(kv * 4 + 2) * GBN + lrow] = cvb[q].z;
            Bs[pb][(kv * 4 + 3) * GBN + lrow] = cvb[q].w;
        }
        __syncthreads();
        if (kt + 1 < Ktiles) {
            #pragma unroll
            for (int q = 0; q < 2; ++q) {
                const int kg = (kt + 1) * GBK + (lkv0 + q) * 4;
                nva[q] = make_float4(0.f, 0.f, 0.f, 0.f);
                nvb[q] = make_float4(0.f, 0.f, 0.f, 0.f);
                if (kg + 3 < Kd) {
                    nva[q] = *(const float4*)(arow_p + kg);
                    if (bvalid) nvb[q] = *(const float4*)(brow_p + kg);
                }
            }
        }
        #pragma unroll
        for (int k = 0; k < GBK; ++k) {
            const float4 a0 = *(const float4*)&As[pb][k * GBM + ty * 4];
            const float4 a1 = *(const float4*)&As[pb][k * GBM + 64 + ty * 4];
            const ulonglong2 b0 = *(const ulonglong2*)&Bs[pb][k * GBN + tx * 4];
            const ulonglong2 b1 = *(const ulonglong2*)&Bs[pb][k * GBN + 64 + tx * 4];
            const ull bv2[4] = {b0.x, b0.y, b1.x, b1.y};
            const float av[8] = {a0.x, a0.y, a0.z, a0.w, a1.x, a1.y, a1.z, a1.w};
            #pragma unroll
            for (int i = 0; i < 8; ++i) {
                const ull av2 = pk2(av[i], av[i]);
                #pragma unroll
                for (int j = 0; j < 4; ++j)
                    acc2[i][j] = ffma2(av2, bv2[j], acc2[i][j]);
            }
        }
        #pragma unroll
        for (int q = 0; q < 2; ++q) { cva[q] = nva[q]; cvb[q] = nvb[q]; }
    }
    #pragma unroll
    for (int i = 0; i < 8; ++i) {
        const int mi = (i < 4) ? (ty * 4 + i) : (64 + ty * 4 + (i - 4));
        const int m  = m0 + mi;
        #pragma unroll
        for (int j = 0; j < 4; ++j) {
            const float2 v = unpk2(acc2[i][j]);
            const int c0 = (j < 2) ? (tx * 4 + 2 * j) : (64 + tx * 4 + 2 * (j - 2));
            const int n1 = n0 + c0, n2 = n0 + c0 + 1;
            if (XGI) {
                C[(size_t)m * N + n1] = v.x + bias[(n1 & 3) * 256 + (n1 >> 2)];
                C[(size_t)m * N + n2] = v.y + bias[(n2 & 3) * 256 + (n2 >> 2)];
            } else {
                if (n1 < N) C[(size_t)m * N + n1] = v.x + bias[n1];
                if (n2 < N) C[(size_t)m * N + n2] = v.y + bias[n2];
            }
        }
    }
}

// ---------------- persistent bidirectional LSTM scan (UNCHANGED from R11) ----------------
// grid = 128 blocks = 2 dirs x 8 batch-groups x 8 unit-slices.
// CTA owns 8 batches x 32 units (all 4 gates); Whh slice (128 rows x 256) in smem.
// Thread map: ul=tid>>3 (local unit 0..31), ks=tid&7 (k-slice AND epilogue batch).
// Barrier only spans the 8 CTAs sharing a batch-group (single atomic counter each).
#define LSTM_SMEM (8 * 65 * 16 + 128 * 264 * 4)   // hs float4[8][65] + Ws[128][264]

__global__ void __launch_bounds__(256)
lstm_scan(const float* __restrict__ xgF, const float* __restrict__ xgBk,
          const float* __restrict__ WhhF, const float* __restrict__ WhhB,
          float* __restrict__ hout)
{
    extern __shared__ char sm_raw[];
    float4* hs = (float4*)sm_raw;                    // [8][65]
    float*  Ws = (float*)(sm_raw + 8 * 65 * 16);     // [128][264]

    const int dir = blockIdx.x >> 6;
    const int loc = blockIdx.x & 63;
    const int bg  = loc >> 3;
    const int us  = loc & 7;
    const int b0  = bg * 8;
    const int u0  = us * 32;
    const int tid = threadIdx.x;
    const int ul  = tid >> 3;
    const int ks  = tid & 7;
    const int unit = u0 + ul;
    const int dof  = dir ? 256 : 0;
    const int bb   = b0 + ks;

    const float* xg  = dir ? xgBk : xgF;
    const float* Whh = dir ? WhhB : WhhF;
    unsigned* bar = &g_bar[(dir * 8 + bg) * 32];

    for (int i = tid; i < 128 * 256; i += 256) {
        const int r = i >> 8, k = i & 255;
        const int g = r >> 5, uu = r & 31;
        Ws[r * 264 + k] = Whh[(size_t)(g * 256 + u0 + uu) * 256 + k];
    }
    __syncthreads();

    const float4* wp0 = (const float4*)&Ws[(0 * 32 + ul) * 264];
    const float4* wp1 = (const float4*)&Ws[(1 * 32 + ul) * 264];
    const float4* wp2 = (const float4*)&Ws[(2 * 32 + ul) * 264];
    const float4* wp3 = (const float4*)&Ws[(3 * 32 + ul) * 264];

    float cc = 0.0f;

    for (int s = 0; s < TQ; ++s) {
        const int t = dir ? (TQ - 1 - s) : s;

        const float4 xq = __ldg((const float4*)(xg + ((size_t)t * BQ + bb) * 1024 + (size_t)unit * 4));

        ull acc2[8][4];
        #pragma unroll
        for (int i = 0; i < 8; ++i)
            #pragma unroll
            for (int g = 0; g < 4; ++g) acc2[i][g] = 0ull;

        if (s > 0) {
            const int tp = dir ? (t + 1) : (t - 1);
            const float* hb = hout + ((size_t)tp * BQ + b0) * 512 + dof;
            #pragma unroll
            for (int j = 0; j < 2; ++j) {
                const int idx = tid + j * 256;
                const int b = idx >> 6, kv = idx & 63;
                hs[b * 65 + kv] = __ldg((const float4*)(hb + (size_t)b * 512 + kv * 4));
            }
            __syncthreads();
            #pragma unroll
            for (int q = 0; q < 8; ++q) {
                const int kv = ks + q * 8;
                const ulonglong2 w0 = *(const ulonglong2*)(wp0 + kv);
                const ulonglong2 w1 = *(const ulonglong2*)(wp1 + kv);
                const ulonglong2 w2 = *(const ulonglong2*)(wp2 + kv);
                const ulonglong2 w3 = *(const ulonglong2*)(wp3 + kv);
                #pragma unroll
                for (int i = 0; i < 8; ++i) {
                    const ulonglong2 h2 = *(const ulonglong2*)&hs[i * 65 + kv];
                    acc2[i][0] = ffma2(h2.x, w0.x, acc2[i][0]);
                    acc2[i][0] = ffma2(h2.y, w0.y, acc2[i][0]);
                    acc2[i][1] = ffma2(h2.x, w1.x, acc2[i][1]);
                    acc2[i][1] = ffma2(h2.y, w1.y, acc2[i][1]);
                    acc2[i][2] = ffma2(h2.x, w2.x, acc2[i][2]);
                    acc2[i][2] = ffma2(h2.y, w2.y, acc2[i][2]);
                    acc2[i][3] = ffma2(h2.x, w3.x, acc2[i][3]);
                    acc2[i][3] = ffma2(h2.y, w3.y, acc2[i][3]);
                }
            }
        }

        float v8[8][4];
        #pragma unroll
        for (int i = 0; i < 8; ++i)
            #pragma unroll
            for (int g = 0; g < 4; ++g) {
                const float2 p = unpk2(acc2[i][g]);
                v8[i][g] = p.x + p.y;
            }
        const bool q2 = (ks & 4) != 0;
        float v4[4][4];
        #pragma unroll
        for (int j = 0; j < 4; ++j)
            #pragma unroll
            for (int g = 0; g < 4; ++g) {
                const float snd = q2 ? v8[j][g] : v8[j + 4][g];
                const float got = __shfl_xor_sync(0xffffffffu, snd, 4);
                v4[j][g] = (q2 ? v8[j + 4][g] : v8[j][g]) + got;
            }
        const bool q1 = (ks & 2) != 0;
        float v2r[2][4];
        #pragma unroll
        for (int j = 0; j < 2; ++j)
            #pragma unroll
            for (int g = 0; g < 4; ++g) {
                const float snd = q1 ? v4[j][g] : v4[j + 2][g];
                const float got = __shfl_xor_sync(0xffffffffu, snd, 2);
                v2r[j][g] = (q1 ? v4[j + 2][g] : v4[j][g]) + got;
            }
        const bool q0 = (ks & 1) != 0;
        float z[4];
        #pragma unroll
        for (int g = 0; g < 4; ++g) {
            const float snd = q0 ? v2r[0][g] : v2r[1][g];
            const float got = __shfl_xor_sync(0xffffffffu, snd, 1);
            z[g] = (q0 ? v2r[1][g] : v2r[0][g]) + got;
        }

        {
            const float zi = z[0] + xq.x;
            const float zf = z[1] + xq.y;
            const float zg = z[2] + xq.z;
            const float zo = z[3] + xq.w;
            const float ig = sigf(zi), fg = sigf(zf), gg = tanh_f(zg), og = sigf(zo);
            cc = fg * cc + ig * gg;
            hout[((size_t)t * BQ + bb) * 512 + dof + unit] = og * tanh_f(cc);
        }

        if (s + 1 < TQ) {
            __threadfence();
            __syncthreads();
            if (tid == 0) {
                atomicAdd(bar, 1u);
                const unsigned target = (unsigned)(s + 1) * 8u;
                while (*((volatile unsigned*)bar) < target) { }
            }
            __syncthreads();
        }
    }
}

// ---------------- CRF: one block per batch ----------------
__global__ void __launch_bounds__(64)
crf_kernel(const int* __restrict__ text, const int* __restrict__ sbj,
           const float* __restrict__ em, const float* __restrict__ start_t,
           const float* __restrict__ end_t, const float* __restrict__ trans,
           float* __restrict__ llh)
{
    const int b   = blockIdx.x;
    const int tid = threadIdx.x;
    __shared__ float tr[KQ * KQ];
    __shared__ float sc[KQ];
    for (int i = tid; i < KQ * KQ; i += 64) tr[i] = trans[i];
    if (tid < KQ) sc[tid] = start_t[tid] + em[(size_t)b * KQ + tid];
    __syncthreads();

    for (int t = 1; t < TQ; ++t) {
        const int tok = text[b * TQ + t];
        if (tok != 0) {
            float nv = 0.0f;
            if (tid < KQ) {
                float mx = -1e30f;
                #pragma unroll 1
                for (int j = 0; j < KQ; ++j) mx = fmaxf(mx, sc[j] + tr[j * KQ + tid]);
                float ssum = 0.0f;
                #pragma unroll 1
                for (int j = 0; j < KQ; ++j) ssum += __expf(sc[j] + tr[j * KQ + tid] - mx);
                nv = em[((size_t)t * BQ + b) * KQ + tid] + mx + __logf(ssum);
            }
            __syncthreads();
            if (tid < KQ) sc[tid] = nv;
            __syncthreads();
        }
    }

    if (tid == 0) {
        float mx = -1e30f;
        for (int k = 0; k < KQ; ++k) mx = fmaxf(mx, sc[k] + end_t[k]);
        float ssum = 0.0f;
        for (int k = 0; k < KQ; ++k) ssum += __expf(sc[k] + end_t[k] - mx);
        const float logZ = mx + __logf(ssum);
        int tag0 = sbj[b * TQ + 0];
        float num = start_t[tag0] + em[(size_t)b * KQ + tag0];
        int prev = tag0, last = tag0;
        for (int t = 1; t < TQ; ++t) {
            if (text[b * TQ + t] != 0) {
                const int tg = sbj[b * TQ + t];
                num += em[((size_t)t * BQ + b) * KQ + tg] + tr[prev * KQ + tg];
                prev = tg; last = tg;
            }
        }
        num += end_t[last];
        llh[b] = num - logZ;
    }
}

// ---------------- finalize ----------------
__global__ void __launch_bounds__(256)
finalize_kernel(const int* __restrict__ text, const float* __restrict__ llh,
                float* __restrict__ out)
{
    __shared__ float sred[256];
    __shared__ float cred[256];
    const int tid = threadIdx.x;
    float s = 0.0f, c = 0.0f;
    for (int i = tid; i < BQ; i += 256) s += llh[i];
    for (int i = tid; i < BQ * TQ; i += 256) c += (text[i] != 0) ? 1.0f : 0.0f;
    sred[tid] = s; cred[tid] = c;
    __syncthreads();
    for (int off = 128; off > 0; off >>= 1) {
        if (tid < off) { sred[tid] += sred[tid + off]; cred[tid] += cred[tid + off]; }
        __syncthreads();
    }
    if (tid == 0) out[0] = -(sred[0] / cred[0]);
}

// ---------------- launch ----------------
extern "C" void kernel_launch(void* const* d_in, const int* in_sizes, int n_in,
                              void* d_out, int out_size)
{
    const int*   text  = (const int*)  d_in[0];
    const int*   sbj   = (const int*)  d_in[1];
    const float* emb   = (const float*)d_in[2];
    const float* Wih0f = (const float*)d_in[3];
    const float* Whh0f = (const float*)d_in[4];
    const float* b0f   = (const float*)d_in[5];
    const float* Wih0b = (const float*)d_in[6];
    const float* Whh0b = (const float*)d_in[7];
    const float* b0b   = (const float*)d_in[8];
    const float* Wih1f = (const float*)d_in[9];
    const float* Whh1f = (const float*)d_in[10];
    const float* b1f   = (const float*)d_in[11];
    const float* Wih1b = (const float*)d_in[12];
    const float* Whh1b = (const float*)d_in[13];
    const float* b1b   = (const float*)d_in[14];
    const float* W_sbj = (const float*)d_in[15];
    const float* b_sbj = (const float*)d_in[16];
    const float* st_t  = (const float*)d_in[17];
    const float* en_t  = (const float*)d_in[18];
    const float* trans = (const float*)d_in[19];
    float* out = (float*)d_out;

    float *xgA, *xgB, *h0, *h1, *em, *llh;
    cudaGetSymbolAddress((void**)&xgA, g_xgA);
    cudaGetSymbolAddress((void**)&xgB, g_xgB);
    cudaGetSymbolAddress((void**)&h0,  g_h0);
    cudaGetSymbolAddress((void**)&h1,  g_h1);
    cudaGetSymbolAddress((void**)&em,  g_em);
    cudaGetSymbolAddress((void**)&llh, g_llh);

    cudaFuncSetAttribute(lstm_scan, cudaFuncAttributeMaxDynamicSharedMemorySize, LSTM_SMEM);

    const dim3 gGemmFull(1024 / GBN, MBQ / GBM);   // (8, 128)
    const dim3 gGemmEm(1, MBQ / GBM);              // (1, 128)  N=37

    gemm_nt_bias<true, true><<<gGemmFull, 256>>>(emb, text, Wih0f, b0f, xgA, MBQ, 1024, DQ, DQ);
    gemm_nt_bias<true, true><<<gGemmFull, 256>>>(emb, text, Wih0b, b0b, xgB, MBQ, 1024, DQ, DQ);
    reset_bar_kernel<<<1, 512>>>();
    lstm_scan<<<128, 256, LSTM_SMEM>>>(xgA, xgB, Whh0f, Whh0b, h0);

    gemm_nt_bias<false, true><<<gGemmFull, 256>>>(h0, nullptr, Wih1f, b1f, xgA, MBQ, 1024, 512, 512);
    gemm_nt_bias<false, true><<<gGemmFull, 256>>>(h0, nullptr, Wih1b, b1b, xgB, MBQ, 1024, 512, 512);
    reset_bar_kernel<<<1, 512>>>();
    lstm_scan<<<128, 256, LSTM_SMEM>>>(xgA, xgB, Whh1f, Whh1b, h1);

    gemm_nt_bias<false, false><<<gGemmEm, 256>>>(h1, nullptr, W_sbj, b_sbj, em, MBQ, KQ, 512, 512);

    crf_kernel<<<BQ, 64>>>(text, sbj, em, st_t, en_t, trans, llh);
    finalize_kernel<<<1, 256>>>(text, llh, out);
}

// round 15
// speedup vs baseline: 2.1701x; 1.0016x over previous
#include <cuda_runtime.h>
#include <cstdint>

// Problem dims (fixed for this instance)
#define BQ 64
#define TQ 256
#define DQ 300
#define HQ 256      // hidden
#define KQ 37       // tags
#define MBQ (TQ*BQ) // 16384 rows (t*B + b)

typedef unsigned long long ull;

// ---------------- scratch (static device globals; no allocation) ----------------
__device__ float g_xgA[(size_t)MBQ * 1024];  // 64 MB (gate-interleaved [t][b][unit][gate])
__device__ float g_xgB[(size_t)MBQ * 1024];  // 64 MB
__device__ float g_h0 [(size_t)MBQ * 512];   // 32 MB
__device__ float g_h1 [(size_t)MBQ * 512];   // 32 MB
__device__ float g_em [(size_t)MBQ * KQ];    // 2.4 MB
__device__ float g_llh[BQ];
__device__ unsigned g_bar[512];              // 16 used counters, padded 128B apart

// ---------------- helpers ----------------
__device__ __forceinline__ float sigf(float x)   { return 1.0f / (1.0f + __expf(-x)); }
__device__ __forceinline__ float tanh_f(float x) { return 2.0f / (1.0f + __expf(-2.0f * x)) - 1.0f; }

__device__ __forceinline__ ull ffma2(ull a, ull b, ull c) {
    ull d;
    asm("fma.rn.f32x2 %0, %1, %2, %3;" : "=l"(d) : "l"(a), "l"(b), "l"(c));
    return d;
}
__device__ __forceinline__ ull pk2(float lo, float hi) {
    ull r;
    asm("mov.b64 %0, {%1, %2};" : "=l"(r) : "f"(lo), "f"(hi));
    return r;
}
__device__ __forceinline__ float2 unpk2(ull v) {
    float2 r;
    asm("mov.b64 {%0, %1}, %2;" : "=f"(r.x), "=f"(r.y) : "l"(v));
    return r;
}

__global__ void reset_bar_kernel() {
    if (threadIdx.x < 512) g_bar[threadIdx.x] = 0u;
}

// ---------------- GEMM: C[M,P] = A(M,K) * Bw'(P,K)^T + bias' ----------------
// 128x128 tile, 16-k, 256 threads, 8x8 microtile via FFMA2, reg prefetch,
// double-buffered smem (ONE sync per k-tile).
// XGI: logical output column p maps to weight/bias row (p&3)*256 + (p>>2)
//      (permutation applied at the B-LOAD, so C stores stay fully coalesced).
#define GBM 128
#define GBN 128
#define GBK 16

template <bool GATHER, bool XGI>
__global__ void __launch_bounds__(256)
gemm_nt_bias(const float* __restrict__ A, const int* __restrict__ textp,
             const float* __restrict__ Bw, const float* __restrict__ bias,
             float* __restrict__ C, int M, int N, int Kd, int lda)
{
    __shared__ float As[2][GBK * GBM];
    __shared__ float Bs[2][GBK * GBN];

    const int tid = threadIdx.x;
    const int m0  = blockIdx.y * GBM;
    const int n0  = blockIdx.x * GBN;
    const int tx  = tid & 15;
    const int ty  = tid >> 4;
    const int lrow = tid >> 1;
    const int lkv0 = (tid & 1) * 2;

    ull acc2[8][4];
    #pragma unroll
    for (int i = 0; i < 8; ++i)
        #pragma unroll
        for (int j = 0; j < 4; ++j) acc2[i][j] = 0ull;

    const float* arow_p;
    {
        const int m = m0 + lrow;
        if (GATHER) {
            const int bb = m & 63;
            const int tt = m >> 6;
            const int tok = textp[bb * TQ + tt];
            arow_p = A + (size_t)tok * lda;
        } else {
            arow_p = A + (size_t)m * lda;
        }
    }
    const int ncol = n0 + lrow;                                     // logical output col
    const int brow = XGI ? ((ncol & 3) * 256 + (ncol >> 2)) : ncol; // weight row
    const float* brow_p = Bw + (size_t)brow * Kd;
    const bool bvalid = ncol < N;

    const int Ktiles = (Kd + GBK - 1) / GBK;

    float4 cva[2], cvb[2], nva[2], nvb[2];
    #pragma unroll
    for (int q = 0; q < 2; ++q) {
        const int kg = (lkv0 + q) * 4;
        cva[q] = make_float4(0.f, 0.f, 0.f, 0.f);
        cvb[q] = make_float4(0.f, 0.f, 0.f, 0.f);
        if (kg + 3 < Kd) {
            cva[q] = *(const float4*)(arow_p + kg);
            if (bvalid) cvb[q] = *(const float4*)(brow_p + kg);
        }
    }

    for (int kt = 0; kt < Ktiles; ++kt) {
        const int pb = kt & 1;
        #pragma unroll
        for (int q = 0; q < 2; ++q) {
            const int kv = lkv0 + q;
            As[pb][(kv * 4 + 0) * GBM + lrow] = cva[q].x;
            As[pb][(kv * 4 + 1) * GBM + lrow] = cva[q].y;
            As[pb][(kv * 4 + 2) * GBM + lrow] = cva[q].z;
            As[pb][(kv * 4 + 3) * GBM + lrow] = cva[q].w;
            Bs[pb][(kv * 4 + 0) * GBN + lrow] = cvb[q].x;
            Bs[pb][(kv * 4 + 1) * GBN + lrow] = cvb[q].y;
            Bs[pb][(kv * 4 + 2) * GBN + lrow] = cvb[q].z;
            Bs[pb][(kv * 4 + 3) * GBN + lrow] = cvb[q].w;
        }
        __syncthreads();
        if (kt + 1 < Ktiles) {
            #pragma unroll
            for (int q = 0; q < 2; ++q) {
                const int kg = (kt + 1) * GBK + (lkv0 + q) * 4;
                nva[q] = make_float4(0.f, 0.f, 0.f, 0.f);
                nvb[q] = make_float4(0.f, 0.f, 0.f, 0.f);
                if (kg + 3 < Kd) {
                    nva[q] = *(const float4*)(arow_p + kg);
                    if (bvalid) nvb[q] = *(const float4*)(brow_p + kg);
                }
            }
        }
        #pragma unroll
        for (int k = 0; k < GBK; ++k) {
            const float4 a0 = *(const float4*)&As[pb][k * GBM + ty * 4];
            const float4 a1 = *(const float4*)&As[pb][k * GBM + 64 + ty * 4];
            const ulonglong2 b0 = *(const ulonglong2*)&Bs[pb][k * GBN + tx * 4];
            const ulonglong2 b1 = *(const ulonglong2*)&Bs[pb][k * GBN + 64 + tx * 4];
            const ull bv2[4] = {b0.x, b0.y, b1.x, b1.y};
            const float av[8] = {a0.x, a0.y, a0.z, a0.w, a1.x, a1.y, a1.z, a1.w};
            #pragma unroll
            for (int i = 0; i < 8; ++i) {
                const ull av2 = pk2(av[i], av[i]);
                #pragma unroll
                for (int j = 0; j < 4; ++j)
                    acc2[i][j] = ffma2(av2, bv2[j], acc2[i][j]);
            }
        }
        #pragma unroll
        for (int q = 0; q < 2; ++q) { cva[q] = nva[q]; cvb[q] = nvb[q]; }
    }
    #pragma unroll
    for (int i = 0; i < 8; ++i) {
        const int mi = (i < 4) ? (ty * 4 + i) : (64 + ty * 4 + (i - 4));
        const int m  = m0 + mi;
        #pragma unroll
        for (int j = 0; j < 4; ++j) {
            const float2 v = unpk2(acc2[i][j]);
            const int c0 = (j < 2) ? (tx * 4 + 2 * j) : (64 + tx * 4 + 2 * (j - 2));
            const int n1 = n0 + c0, n2 = n0 + c0 + 1;
            if (XGI) {
                C[(size_t)m * N + n1] = v.x + bias[(n1 & 3) * 256 + (n1 >> 2)];
                C[(size_t)m * N + n2] = v.y + bias[(n2 & 3) * 256 + (n2 >> 2)];
            } else {
                if (n1 < N) C[(size_t)m * N + n1] = v.x + bias[n1];
                if (n2 < N) C[(size_t)m * N + n2] = v.y + bias[n2];
            }
        }
    }
}

// ---------------- persistent bidirectional LSTM scan ----------------
// grid = 128 blocks = 2 dirs x 8 batch-groups x 8 unit-slices.
// CTA owns 8 batches x 32 units (all 4 gates); Whh slice (128 rows x 256) in smem.
// Thread map: ul=tid>>3 (local unit 0..31), ks=tid&7 (k-slice AND epilogue batch).
// Barrier spans only the 8 CTAs of a batch-group; arrival via red.release.gpu and
// poll via ld.acquire.gpu (NO __threadfence -> no per-step CCTL.IVALL L1 flush).
#define LSTM_SMEM (8 * 65 * 16 + 128 * 264 * 4)   // hs float4[8][65] + Ws[128][264]

__global__ void __launch_bounds__(256)
lstm_scan(const float* __restrict__ xgF, const float* __restrict__ xgBk,
          const float* __restrict__ WhhF, const float* __restrict__ WhhB,
          float* __restrict__ hout)
{
    extern __shared__ char sm_raw[];
    float4* hs = (float4*)sm_raw;                    // [8][65]
    float*  Ws = (float*)(sm_raw + 8 * 65 * 16);     // [128][264]

    const int dir = blockIdx.x >> 6;
    const int loc = blockIdx.x & 63;
    const int bg  = loc >> 3;
    const int us  = loc & 7;
    const int b0  = bg * 8;
    const int u0  = us * 32;
    const int tid = threadIdx.x;
    const int ul  = tid >> 3;
    const int ks  = tid & 7;
    const int unit = u0 + ul;
    const int dof  = dir ? 256 : 0;
    const int bb   = b0 + ks;

    const float* xg  = dir ? xgBk : xgF;
    const float* Whh = dir ? WhhB : WhhF;
    unsigned* bar = &g_bar[(dir * 8 + bg) * 32];

    for (int i = tid; i < 128 * 256; i += 256) {
        const int r = i >> 8, k = i & 255;
        const int g = r >> 5, uu = r & 31;
        Ws[r * 264 + k] = Whh[(size_t)(g * 256 + u0 + uu) * 256 + k];
    }
    __syncthreads();

    const float4* wp0 = (const float4*)&Ws[(0 * 32 + ul) * 264];
    const float4* wp1 = (const float4*)&Ws[(1 * 32 + ul) * 264];
    const float4* wp2 = (const float4*)&Ws[(2 * 32 + ul) * 264];
    const float4* wp3 = (const float4*)&Ws[(3 * 32 + ul) * 264];

    float cc = 0.0f;

    for (int s = 0; s < TQ; ++s) {
        const int t = dir ? (TQ - 1 - s) : s;

        // xg prefetch: ONE float4 = 4 gate inputs for (bb, unit) (interleaved layout)
        const float4 xq = __ldg((const float4*)(xg + ((size_t)t * BQ + bb) * 1024 + (size_t)unit * 4));

        ull acc2[8][4];
        #pragma unroll
        for (int i = 0; i < 8; ++i)
            #pragma unroll
            for (int g = 0; g < 4; ++g) acc2[i][g] = 0ull;

        if (s > 0) {
            // stage h_prev for OUR 8 batches (this direction) into smem, coalesced
            const int tp = dir ? (t + 1) : (t - 1);
            const float* hb = hout + ((size_t)tp * BQ + b0) * 512 + dof;
            #pragma unroll
            for (int j = 0; j < 2; ++j) {
                const int idx = tid + j * 256;
                const int b = idx >> 6, kv = idx & 63;
                hs[b * 65 + kv] = __ldg((const float4*)(hb + (size_t)b * 512 + kv * 4));
            }
            __syncthreads();
            // mat-vec from smem, k-pairs in f32x2 lanes
            #pragma unroll
            for (int q = 0; q < 8; ++q) {
                const int kv = ks + q * 8;
                const ulonglong2 w0 = *(const ulonglong2*)(wp0 + kv);
                const ulonglong2 w1 = *(const ulonglong2*)(wp1 + kv);
                const ulonglong2 w2 = *(const ulonglong2*)(wp2 + kv);
                const ulonglong2 w3 = *(const ulonglong2*)(wp3 + kv);
                #pragma unroll
                for (int i = 0; i < 8; ++i) {
                    const ulonglong2 h2 = *(const ulonglong2*)&hs[i * 65 + kv];
                    acc2[i][0] = ffma2(h2.x, w0.x, acc2[i][0]);
                    acc2[i][0] = ffma2(h2.y, w0.y, acc2[i][0]);
                    acc2[i][1] = ffma2(h2.x, w1.x, acc2[i][1]);
                    acc2[i][1] = ffma2(h2.y, w1.y, acc2[i][1]);
                    acc2[i][2] = ffma2(h2.x, w2.x, acc2[i][2]);
                    acc2[i][2] = ffma2(h2.y, w2.y, acc2[i][2]);
                    acc2[i][3] = ffma2(h2.x, w3.x, acc2[i][3]);
                    acc2[i][3] = ffma2(h2.y, w3.y, acc2[i][3]);
                }
            }
        }

        // ---- value-routed butterfly over ks lanes: lane ks ends owning batch ks ----
        float v8[8][4];
        #pragma unroll
        for (int i = 0; i < 8; ++i)
            #pragma unroll
            for (int g = 0; g < 4; ++g) {
                const float2 p = unpk2(acc2[i][g]);
                v8[i][g] = p.x + p.y;
            }
        const bool q2 = (ks & 4) != 0;
        float v4[4][4];
        #pragma unroll
        for (int j = 0; j < 4; ++j)
            #pragma unroll
            for (int g = 0; g < 4; ++g) {
                const float snd = q2 ? v8[j][g] : v8[j + 4][g];
                const float got = __shfl_xor_sync(0xffffffffu, snd, 4);
                v4[j][g] = (q2 ? v8[j + 4][g] : v8[j][g]) + got;
            }
        const bool q1 = (ks & 2) != 0;
        float v2r[2][4];
        #pragma unroll
        for (int j = 0; j < 2; ++j)
            #pragma unroll
            for (int g = 0; g < 4; ++g) {
                const float snd = q1 ? v4[j][g] : v4[j + 2][g];
                const float got = __shfl_xor_sync(0xffffffffu, snd, 2);
                v2r[j][g] = (q1 ? v4[j + 2][g] : v4[j][g]) + got;
            }
        const bool q0 = (ks & 1) != 0;
        float z[4];
        #pragma unroll
        for (int g = 0; g < 4; ++g) {
            const float snd = q0 ? v2r[0][g] : v2r[1][g];
            const float got = __shfl_xor_sync(0xffffffffu, snd, 1);
            z[g] = (q0 ? v2r[1][g] : v2r[0][g]) + got;
        }

        // ---- fully parallel epilogue: one LSTM cell per thread ----
        {
            const float zi = z[0] + xq.x;
            const float zf = z[1] + xq.y;
            const float zg = z[2] + xq.z;
            const float zo = z[3] + xq.w;
            const float ig = sigf(zi), fg = sigf(zf), gg = tanh_f(zg), og = sigf(zo);
            cc = fg * cc + ig * gg;
            hout[((size_t)t * BQ + bb) * 512 + dof + unit] = og * tanh_f(cc);
        }

        // ---- inter-CTA step barrier: release-arrive / acquire-poll (no L1 flush) ----
        if (s + 1 < TQ) {
            __syncthreads();   // all h stores of this CTA issued before the release
            if (tid == 0) {
                asm volatile("red.release.gpu.global.add.u32 [%0], %1;"
                             :: "l"(bar), "r"(1u) : "memory");
                const unsigned target = (unsigned)(s + 1) * 8u;
                unsigned v;
                do {
                    asm volatile("ld.acquire.gpu.global.u32 %0, [%1];"
                                 : "=r"(v) : "l"(bar) : "memory");
                } while (v < target);
            }
            __syncthreads();
        }
    }
}

// ---------------- CRF: one block per batch ----------------
__global__ void __launch_bounds__(64)
crf_kernel(const int* __restrict__ text, const int* __restrict__ sbj,
           const float* __restrict__ em, const float* __restrict__ start_t,
           const float* __restrict__ end_t, const float* __restrict__ trans,
           float* __restrict__ llh)
{
    const int b   = blockIdx.x;
    const int tid = threadIdx.x;
    __shared__ float tr[KQ * KQ];
    __shared__ float sc[KQ];
    for (int i = tid; i < KQ * KQ; i += 64) tr[i] = trans[i];
    if (tid < KQ) sc[tid] = start_t[tid] + em[(size_t)b * KQ + tid];
    __syncthreads();

    for (int t = 1; t < TQ; ++t) {
        const int tok = text[b * TQ + t];
        if (tok != 0) {
            float nv = 0.0f;
            if (tid < KQ) {
                float mx = -1e30f;
                #pragma unroll 1
                for (int j = 0; j < KQ; ++j) mx = fmaxf(mx, sc[j] + tr[j * KQ + tid]);
                float ssum = 0.0f;
                #pragma unroll 1
                for (int j = 0; j < KQ; ++j) ssum += __expf(sc[j] + tr[j * KQ + tid] - mx);
                nv = em[((size_t)t * BQ + b) * KQ + tid] + mx + __logf(ssum);
            }
            __syncthreads();
            if (tid < KQ) sc[tid] = nv;
            __syncthreads();
        }
    }

    if (tid == 0) {
        float mx = -1e30f;
        for (int k = 0; k < KQ; ++k) mx = fmaxf(mx, sc[k] + end_t[k]);
        float ssum = 0.0f;
        for (int k = 0; k < KQ; ++k) ssum += __expf(sc[k] + end_t[k] - mx);
        const float logZ = mx + __logf(ssum);
        int tag0 = sbj[b * TQ + 0];
        float num = start_t[tag0] + em[(size_t)b * KQ + tag0];
        int prev = tag0, last = tag0;
        for (int t = 1; t < TQ; ++t) {
            if (text[b * TQ + t] != 0) {
                const int tg = sbj[b * TQ + t];
                num += em[((size_t)t * BQ + b) * KQ + tg] + tr[prev * KQ + tg];
                prev = tg; last = tg;
            }
        }
        num += end_t[last];
        llh[b] = num - logZ;
    }
}

// ---------------- finalize ----------------
__global__ void __launch_bounds__(256)
finalize_kernel(const int* __restrict__ text, const float* __restrict__ llh,
                float* __restrict__ out)
{
    __shared__ float sred[256];
    __shared__ float cred[256];
    const int tid = threadIdx.x;
    float s = 0.0f, c = 0.0f;
    for (int i = tid; i < BQ; i += 256) s += llh[i];
    for (int i = tid; i < BQ * TQ; i += 256) c += (text[i] != 0) ? 1.0f : 0.0f;
    sred[tid] = s; cred[tid] = c;
    __syncthreads();
    for (int off = 128; off > 0; off >>= 1) {
        if (tid < off) { sred[tid] += sred[tid + off]; cred[tid] += cred[tid + off]; }
        __syncthreads();
    }
    if (tid == 0) out[0] = -(sred[0] / cred[0]);
}

// ---------------- launch ----------------
extern "C" void kernel_launch(void* const* d_in, const int* in_sizes, int n_in,
                              void* d_out, int out_size)
{
    const int*   text  = (const int*)  d_in[0];
    const int*   sbj   = (const int*)  d_in[1];
    const float* emb   = (const float*)d_in[2];
    const float* Wih0f = (const float*)d_in[3];
    const float* Whh0f = (const float*)d_in[4];
    const float* b0f   = (const float*)d_in[5];
    const float* Wih0b = (const float*)d_in[6];
    const float* Whh0b = (const float*)d_in[7];
    const float* b0b   = (const float*)d_in[8];
    const float* Wih1f = (const float*)d_in[9];
    const float* Whh1f = (const float*)d_in[10];
    const float* b1f   = (const float*)d_in[11];
    const float* Wih1b = (const float*)d_in[12];
    const float* Whh1b = (const float*)d_in[13];
    const float* b1b   = (const float*)d_in[14];
    const float* W_sbj = (const float*)d_in[15];
    const float* b_sbj = (const float*)d_in[16];
    const float* st_t  = (const float*)d_in[17];
    const float* en_t  = (const float*)d_in[18];
    const float* trans = (const float*)d_in[19];
    float* out = (float*)d_out;

    float *xgA, *xgB, *h0, *h1, *em, *llh;
    cudaGetSymbolAddress((void**)&xgA, g_xgA);
    cudaGetSymbolAddress((void**)&xgB, g_xgB);
    cudaGetSymbolAddress((void**)&h0,  g_h0);
    cudaGetSymbolAddress((void**)&h1,  g_h1);
    cudaGetSymbolAddress((void**)&em,  g_em);
    cudaGetSymbolAddress((void**)&llh, g_llh);

    cudaFuncSetAttribute(lstm_scan, cudaFuncAttributeMaxDynamicSharedMemorySize, LSTM_SMEM);

    const dim3 gGemmFull(1024 / GBN, MBQ / GBM);   // (8, 128)
    const dim3 gGemmEm(1, MBQ / GBM);              // (1, 128)  N=37

    gemm_nt_bias<true, true><<<gGemmFull, 256>>>(emb, text, Wih0f, b0f, xgA, MBQ, 1024, DQ, DQ);
    gemm_nt_bias<true, true><<<gGemmFull, 256>>>(emb, text, Wih0b, b0b, xgB, MBQ, 1024, DQ, DQ);
    reset_bar_kernel<<<1, 512>>>();
    lstm_scan<<<128, 256, LSTM_SMEM>>>(xgA, xgB, Whh0f, Whh0b, h0);

    gemm_nt_bias<false, true><<<gGemmFull, 256>>>(h0, nullptr, Wih1f, b1f, xgA, MBQ, 1024, 512, 512);
    gemm_nt_bias<false, true><<<gGemmFull, 256>>>(h0, nullptr, Wih1b, b1b, xgB, MBQ, 1024, 512, 512);
    reset_bar_kernel<<<1, 512>>>();
    lstm_scan<<<128, 256, LSTM_SMEM>>>(xgA, xgB, Whh1f, Whh1b, h1);

    gemm_nt_bias<false, false><<<gGemmEm, 256>>>(h1, nullptr, W_sbj, b_sbj, em, MBQ, KQ, 512, 512);

    crf_kernel<<<BQ, 64>>>(text, sbj, em, st_t, en_t, trans, llh);
    finalize_kernel<<<1, 256>>>(text, llh, out);
}